// round 9
// baseline (speedup 1.0000x reference)
#include <cuda_runtime.h>
#include <cuda_bf16.h>
#include <math.h>
#include <stdint.h>

#define Bq 64
#define Sq 128
#define Eq 512
#define Hq 1024
#define Vq 50257
#define KIq (Eq + Hq)   /* 1536 */
#define G4q (4 * Hq)    /* 4096 */
#define SBq (Sq * Bq)   /* 8192 */
#define NSLOT 32

// ---------------- scratch (static device globals; no runtime allocation) ----
__device__ float g_hW[Bq * Hq];
__device__ float g_spart[NSLOT * SBq];  // score column-partials per (s,b) row
__device__ float g_ctx[Bq * Hq];
__device__ float g_x[Bq * KIq];
__device__ float g_gates[Bq * G4q];

// ---------------- precision helpers -----------------------------------------
__device__ __forceinline__ unsigned f2tf32(float x)
{
    unsigned r;
    asm("cvt.rna.tf32.f32 %0, %1;" : "=r"(r) : "f"(x));
    return r;
}

__device__ __forceinline__ void split_bf16(float x, float& hi, float& lo)
{
    hi = __bfloat162float(__float2bfloat16(x));
    lo = x - hi;
}

// pack two floats as bf16x2: low 16 bits = e0, high = e1
__device__ __forceinline__ unsigned pack2(float e0, float e1)
{
    unsigned r;
    asm("cvt.rn.bf16x2.f32 %0, %1, %2;" : "=r"(r) : "f"(e1), "f"(e0));
    return r;
}

__device__ __forceinline__ void mma_bf16(float c[4], const unsigned a[4],
                                         const unsigned b[2])
{
    asm volatile(
        "mma.sync.aligned.m16n8k16.row.col.f32.bf16.bf16.f32 "
        "{%0,%1,%2,%3}, {%4,%5,%6,%7}, {%8,%9}, {%0,%1,%2,%3};"
        : "+f"(c[0]), "+f"(c[1]), "+f"(c[2]), "+f"(c[3])
        : "r"(a[0]), "r"(a[1]), "r"(a[2]), "r"(a[3]), "r"(b[0]), "r"(b[1]));
}

__device__ __forceinline__ void mma_tf32(float c[4], const unsigned a[4],
                                         const unsigned b[2])
{
    asm volatile(
        "mma.sync.aligned.m16n8k8.row.col.f32.tf32.tf32.f32 "
        "{%0,%1,%2,%3}, {%4,%5,%6,%7}, {%8,%9}, {%0,%1,%2,%3};"
        : "+f"(c[0]), "+f"(c[1]), "+f"(c[2]), "+f"(c[3])
        : "r"(a[0]), "r"(a[1]), "r"(a[2]), "r"(a[3]), "r"(b[0]), "r"(b[1]));
}

__device__ __forceinline__ float tanh_fast(float x)
{
    float cx = fminf(fmaxf(x, -15.f), 15.f);
    float e = __expf(2.f * cx);
    return __fdividef(e - 1.f, e + 1.f);
}

// ================== 3xBF16 GEMM template (hi/lo compensated) ================
// C[M,N] = A[M,K] @ B[N,K]^T (+bias)(+=C). M%BM==0, K%BK==0, N ragged.
// n_off shifts the n-block origin (for split launches).
template <int BM, int BN, int BK, int WM, int WN>
__global__ void __launch_bounds__(256)
mma3bf_gemm_nt(const float* __restrict__ A, const float* __restrict__ Bm,
               float* __restrict__ C, int M, int N, int K,
               const float* __restrict__ bias, int accum, int n_off)
{
    constexpr int MI = WM / 16;
    constexpr int NI = WN / 8;
    constexpr int PP = BK / 2;          // pairs per row
    constexpr int KPP = PP + 4;         // padded pairs
    constexpr int F4R = BK / 4;         // float4 loads per row
    constexpr int RPP = 256 / F4R;

    __shared__ unsigned Ah[BM][KPP], Al[BM][KPP];
    __shared__ unsigned Bh[BN][KPP], Bl[BN][KPP];

    const int tid = threadIdx.x;
    const int lane = tid & 31;
    const int w = tid >> 5;
    const int warp_m = (w % (BM / WM)) * WM;
    const int warp_n = (w / (BM / WM)) * WN;
    const int m0 = blockIdx.y * BM;
    const int n0 = blockIdx.x * BN + n_off;
    const int lrow = tid / F4R;
    const int lk4 = (tid % F4R) * 4;    // float offset
    const int lp = lk4 >> 1;            // pair offset

    float acc[MI][NI][4];
#pragma unroll
    for (int i = 0; i < MI; i++)
#pragma unroll
        for (int j = 0; j < NI; j++)
#pragma unroll
            for (int q = 0; q < 4; q++) acc[i][j][q] = 0.f;

    for (int k0 = 0; k0 < K; k0 += BK) {
#pragma unroll
        for (int r = lrow; r < BM; r += RPP) {
            float4 vv = *reinterpret_cast<const float4*>(
                A + (size_t)(m0 + r) * K + k0 + lk4);
            float hx, lx, hy, ly, hz, lz, hw, lw;
            split_bf16(vv.x, hx, lx); split_bf16(vv.y, hy, ly);
            split_bf16(vv.z, hz, lz); split_bf16(vv.w, hw, lw);
            Ah[r][lp] = pack2(hx, hy); Ah[r][lp + 1] = pack2(hz, hw);
            Al[r][lp] = pack2(lx, ly); Al[r][lp + 1] = pack2(lz, lw);
        }
#pragma unroll
        for (int r = lrow; r < BN; r += RPP) {
            float4 vv = make_float4(0.f, 0.f, 0.f, 0.f);
            if (n0 + r < N)
                vv = *reinterpret_cast<const float4*>(
                    Bm + (size_t)(n0 + r) * K + k0 + lk4);
            float hx, lx, hy, ly, hz, lz, hw, lw;
            split_bf16(vv.x, hx, lx); split_bf16(vv.y, hy, ly);
            split_bf16(vv.z, hz, lz); split_bf16(vv.w, hw, lw);
            Bh[r][lp] = pack2(hx, hy); Bh[r][lp + 1] = pack2(hz, hw);
            Bl[r][lp] = pack2(lx, ly); Bl[r][lp + 1] = pack2(lz, lw);
        }
        __syncthreads();

#pragma unroll
        for (int kk = 0; kk < PP; kk += 8) {
            unsigned ah[MI][4], al[MI][4], bh[NI][2], bl[NI][2];
#pragma unroll
            for (int i = 0; i < MI; i++) {
                int r = warp_m + i * 16 + (lane >> 2);
                int cb = kk + (lane & 3);
                ah[i][0] = Ah[r][cb];     ah[i][1] = Ah[r + 8][cb];
                ah[i][2] = Ah[r][cb + 4]; ah[i][3] = Ah[r + 8][cb + 4];
                al[i][0] = Al[r][cb];     al[i][1] = Al[r + 8][cb];
                al[i][2] = Al[r][cb + 4]; al[i][3] = Al[r + 8][cb + 4];
            }
#pragma unroll
            for (int j = 0; j < NI; j++) {
                int r = warp_n + j * 8 + (lane >> 2);
                int cb = kk + (lane & 3);
                bh[j][0] = Bh[r][cb]; bh[j][1] = Bh[r][cb + 4];
                bl[j][0] = Bl[r][cb]; bl[j][1] = Bl[r][cb + 4];
            }
#pragma unroll
            for (int i = 0; i < MI; i++)
#pragma unroll
                for (int j = 0; j < NI; j++) {
                    mma_bf16(acc[i][j], ah[i], bl[j]);
                    mma_bf16(acc[i][j], al[i], bh[j]);
                    mma_bf16(acc[i][j], ah[i], bh[j]);
                }
        }
        __syncthreads();
    }

#pragma unroll
    for (int i = 0; i < MI; i++)
#pragma unroll
        for (int j = 0; j < NI; j++) {
            int row = m0 + warp_m + i * 16 + (lane >> 2);
            int col = n0 + warp_n + j * 8 + 2 * (lane & 3);
#pragma unroll
            for (int q = 0; q < 4; q++) {
                int gr = row + (q >> 1) * 8;
                int gc = col + (q & 1);
                if (gc < N) {
                    float r = acc[i][j][q];
                    if (bias) r += bias[gc];
                    size_t off = (size_t)gr * N + gc;
                    if (accum) r += C[off];
                    C[off] = r;
                }
            }
        }
}

// ============ 3xBF16 energy GEMM + fused score, double-buffered =============
// T = enc[8192,1024] @ U[1024,1024]^T; fused score partials out (32 slots).
// BM=128, BN=64, BK=32; warp grid 4(M)x2(N), warp tile 32x32 (MI=2, NI=4).
// Double-buffered smem: LDG prefetch of chunk n+1 issues before the MMA phase
// of chunk n; split+STS after; one __syncthreads per chunk.
#define T_KPP 20
#define T_AL 2560            /* 128*20 */
#define T_BH 5120
#define T_BL 6400            /* + 64*20 */
#define T_BUF 7680           /* u32 per buffer */
#define T_SMEM (2 * T_BUF * 4)   /* 61440 B */

__global__ void __launch_bounds__(256, 2)
tgemm_score_kernel(const float* __restrict__ enc, const float* __restrict__ U,
                   const float* __restrict__ Ub, const float* __restrict__ v)
{
    extern __shared__ unsigned smt[];
    constexpr int MI = 2, NI = 4;

    const int tid = threadIdx.x;
    const int lane = tid & 31;
    const int w = tid >> 5;
    const int lane4 = lane >> 2;
    const int lanek = lane & 3;
    const int warp_m = (w & 3) * 32;
    const int warp_n = (w >> 2) * 32;
    const int m0 = blockIdx.y * 128;
    const int n0 = blockIdx.x * 64;
    const int lrow = tid >> 3;          // 0..31
    const int lk4 = (tid & 7) * 4;
    const int lp = lk4 >> 1;

    const float* Abase = enc + (size_t)(m0 + lrow) * Hq + lk4;
    const float* Bbase = U + (size_t)(n0 + lrow) * Hq + lk4;

    float acc[MI][NI][4];
#pragma unroll
    for (int i = 0; i < MI; i++)
#pragma unroll
        for (int j = 0; j < NI; j++)
#pragma unroll
            for (int q = 0; q < 4; q++) acc[i][j][q] = 0.f;

    float4 pa[4], pb[2];
    // prefetch chunk 0
#pragma unroll
    for (int u = 0; u < 4; u++)
        pa[u] = *reinterpret_cast<const float4*>(Abase + (size_t)u * 32 * Hq);
#pragma unroll
    for (int u = 0; u < 2; u++)
        pb[u] = *reinterpret_cast<const float4*>(Bbase + (size_t)u * 32 * Hq);

    // split + store chunk 0 into buffer 0
    {
        unsigned* nb = smt;
#pragma unroll
        for (int u = 0; u < 4; u++) {
            int r = lrow + u * 32;
            float hx, lx, hy, ly, hz, lz, hw, lw;
            split_bf16(pa[u].x, hx, lx); split_bf16(pa[u].y, hy, ly);
            split_bf16(pa[u].z, hz, lz); split_bf16(pa[u].w, hw, lw);
            nb[r * T_KPP + lp] = pack2(hx, hy);
            nb[r * T_KPP + lp + 1] = pack2(hz, hw);
            nb[T_AL + r * T_KPP + lp] = pack2(lx, ly);
            nb[T_AL + r * T_KPP + lp + 1] = pack2(lz, lw);
        }
#pragma unroll
        for (int u = 0; u < 2; u++) {
            int r = lrow + u * 32;
            float hx, lx, hy, ly, hz, lz, hw, lw;
            split_bf16(pb[u].x, hx, lx); split_bf16(pb[u].y, hy, ly);
            split_bf16(pb[u].z, hz, lz); split_bf16(pb[u].w, hw, lw);
            nb[T_BH + r * T_KPP + lp] = pack2(hx, hy);
            nb[T_BH + r * T_KPP + lp + 1] = pack2(hz, hw);
            nb[T_BL + r * T_KPP + lp] = pack2(lx, ly);
            nb[T_BL + r * T_KPP + lp + 1] = pack2(lz, lw);
        }
    }
    __syncthreads();

    for (int ch = 0; ch < 32; ch++) {
        const unsigned* base = smt + (ch & 1) * T_BUF;

        // issue LDGs for chunk ch+1 (latency hidden under MMA phase)
        if (ch < 31) {
            const float* An = Abase + (ch + 1) * 32;
            const float* Bn = Bbase + (ch + 1) * 32;
#pragma unroll
            for (int u = 0; u < 4; u++)
                pa[u] = *reinterpret_cast<const float4*>(
                    An + (size_t)u * 32 * Hq);
#pragma unroll
            for (int u = 0; u < 2; u++)
                pb[u] = *reinterpret_cast<const float4*>(
                    Bn + (size_t)u * 32 * Hq);
        }

        // MMA phase on buffer (ch & 1)
#pragma unroll
        for (int kk = 0; kk < 16; kk += 8) {
            unsigned ah[MI][4], al[MI][4], bh[NI][2], bl[NI][2];
#pragma unroll
            for (int i = 0; i < MI; i++) {
                int r = warp_m + i * 16 + lane4;
                int cb = kk + lanek;
                ah[i][0] = base[r * T_KPP + cb];
                ah[i][1] = base[(r + 8) * T_KPP + cb];
                ah[i][2] = base[r * T_KPP + cb + 4];
                ah[i][3] = base[(r + 8) * T_KPP + cb + 4];
                al[i][0] = base[T_AL + r * T_KPP + cb];
                al[i][1] = base[T_AL + (r + 8) * T_KPP + cb];
                al[i][2] = base[T_AL + r * T_KPP + cb + 4];
                al[i][3] = base[T_AL + (r + 8) * T_KPP + cb + 4];
            }
#pragma unroll
            for (int j = 0; j < NI; j++) {
                int r = warp_n + j * 8 + lane4;
                int cb = kk + lanek;
                bh[j][0] = base[T_BH + r * T_KPP + cb];
                bh[j][1] = base[T_BH + r * T_KPP + cb + 4];
                bl[j][0] = base[T_BL + r * T_KPP + cb];
                bl[j][1] = base[T_BL + r * T_KPP + cb + 4];
            }
#pragma unroll
            for (int i = 0; i < MI; i++)
#pragma unroll
                for (int j = 0; j < NI; j++) {
                    mma_bf16(acc[i][j], ah[i], bl[j]);
                    mma_bf16(acc[i][j], al[i], bh[j]);
                    mma_bf16(acc[i][j], ah[i], bh[j]);
                }
        }

        // split + store chunk ch+1 into the other buffer
        if (ch < 31) {
            unsigned* nb = smt + ((ch + 1) & 1) * T_BUF;
#pragma unroll
            for (int u = 0; u < 4; u++) {
                int r = lrow + u * 32;
                float hx, lx, hy, ly, hz, lz, hw, lw;
                split_bf16(pa[u].x, hx, lx); split_bf16(pa[u].y, hy, ly);
                split_bf16(pa[u].z, hz, lz); split_bf16(pa[u].w, hw, lw);
                nb[r * T_KPP + lp] = pack2(hx, hy);
                nb[r * T_KPP + lp + 1] = pack2(hz, hw);
                nb[T_AL + r * T_KPP + lp] = pack2(lx, ly);
                nb[T_AL + r * T_KPP + lp + 1] = pack2(lz, lw);
            }
#pragma unroll
            for (int u = 0; u < 2; u++) {
                int r = lrow + u * 32;
                float hx, lx, hy, ly, hz, lz, hw, lw;
                split_bf16(pb[u].x, hx, lx); split_bf16(pb[u].y, hy, ly);
                split_bf16(pb[u].z, hz, lz); split_bf16(pb[u].w, hw, lw);
                nb[T_BH + r * T_KPP + lp] = pack2(hx, hy);
                nb[T_BH + r * T_KPP + lp + 1] = pack2(hz, hw);
                nb[T_BL + r * T_KPP + lp] = pack2(lx, ly);
                nb[T_BL + r * T_KPP + lp + 1] = pack2(lz, lw);
            }
        }
        __syncthreads();
    }

    // ---- fused score epilogue over this warp's 32 columns ------------------
    float vv[NI][2], uu[NI][2];
#pragma unroll
    for (int j = 0; j < NI; j++)
#pragma unroll
        for (int qc = 0; qc < 2; qc++) {
            int c = n0 + warp_n + j * 8 + 2 * lanek + qc;
            vv[j][qc] = v[c];
            uu[j][qc] = Ub[c];
        }

    const int slot = blockIdx.x * 2 + (w >> 2);   // 16 blocks x 2 n-warps = 32
#pragma unroll
    for (int i = 0; i < MI; i++)
#pragma unroll
        for (int qr = 0; qr < 2; qr++) {
            int row = m0 + warp_m + i * 16 + lane4 + qr * 8;
            int b = row & (Bq - 1);
            const float* hwr = g_hW + (size_t)b * Hq + n0 + warp_n + 2 * lanek;
            float part = 0.f;
#pragma unroll
            for (int j = 0; j < NI; j++)
#pragma unroll
                for (int qc = 0; qc < 2; qc++) {
                    float t = acc[i][j][2 * qr + qc] + uu[j][qc]
                              + hwr[j * 8 + qc];
                    part += vv[j][qc] * tanh_fast(t);
                }
            part += __shfl_xor_sync(0xffffffffu, part, 1);
            part += __shfl_xor_sync(0xffffffffu, part, 2);
            if (lanek == 0)
                g_spart[(size_t)slot * SBq + row] = part;
        }
}

// ================== single-pass tf32 GEMM (logits) ==========================
template <int BM, int BN, int BK, int WM, int WN>
__global__ void __launch_bounds__(256)
mma_gemm_nt(const float* __restrict__ A, const float* __restrict__ Bm,
            float* __restrict__ C, int M, int N, int K,
            const float* __restrict__ bias)
{
    constexpr int MI = WM / 16;
    constexpr int NI = WN / 8;
    constexpr int KP = BK + 4;
    constexpr int F4R = BK / 4;
    constexpr int RPP = 256 / F4R;

    __shared__ unsigned As[BM][KP];
    __shared__ unsigned Bs[BN][KP];

    const int tid = threadIdx.x;
    const int lane = tid & 31;
    const int w = tid >> 5;
    const int warp_m = (w % (BM / WM)) * WM;
    const int warp_n = (w / (BM / WM)) * WN;
    const int m0 = blockIdx.y * BM;
    const int n0 = blockIdx.x * BN;
    const int lrow = tid / F4R;
    const int lk4 = (tid % F4R) * 4;

    float acc[MI][NI][4];
#pragma unroll
    for (int i = 0; i < MI; i++)
#pragma unroll
        for (int j = 0; j < NI; j++)
#pragma unroll
            for (int q = 0; q < 4; q++) acc[i][j][q] = 0.f;

    for (int k0 = 0; k0 < K; k0 += BK) {
#pragma unroll
        for (int r = lrow; r < BM; r += RPP) {
            float4 vv = *reinterpret_cast<const float4*>(
                A + (size_t)(m0 + r) * K + k0 + lk4);
            uint4 u;
            u.x = f2tf32(vv.x); u.y = f2tf32(vv.y);
            u.z = f2tf32(vv.z); u.w = f2tf32(vv.w);
            *reinterpret_cast<uint4*>(&As[r][lk4]) = u;
        }
#pragma unroll
        for (int r = lrow; r < BN; r += RPP) {
            float4 vv = make_float4(0.f, 0.f, 0.f, 0.f);
            if (n0 + r < N)
                vv = *reinterpret_cast<const float4*>(
                    Bm + (size_t)(n0 + r) * K + k0 + lk4);
            uint4 u;
            u.x = f2tf32(vv.x); u.y = f2tf32(vv.y);
            u.z = f2tf32(vv.z); u.w = f2tf32(vv.w);
            *reinterpret_cast<uint4*>(&Bs[r][lk4]) = u;
        }
        __syncthreads();

#pragma unroll
        for (int kk = 0; kk < BK; kk += 8) {
            unsigned af[MI][4], bf[NI][2];
#pragma unroll
            for (int i = 0; i < MI; i++) {
                int r = warp_m + i * 16 + (lane >> 2);
                int cb = kk + (lane & 3);
                af[i][0] = As[r][cb];     af[i][1] = As[r + 8][cb];
                af[i][2] = As[r][cb + 4]; af[i][3] = As[r + 8][cb + 4];
            }
#pragma unroll
            for (int j = 0; j < NI; j++) {
                int r = warp_n + j * 8 + (lane >> 2);
                int cb = kk + (lane & 3);
                bf[j][0] = Bs[r][cb]; bf[j][1] = Bs[r][cb + 4];
            }
#pragma unroll
            for (int i = 0; i < MI; i++)
#pragma unroll
                for (int j = 0; j < NI; j++)
                    mma_tf32(acc[i][j], af[i], bf[j]);
        }
        __syncthreads();
    }

#pragma unroll
    for (int i = 0; i < MI; i++)
#pragma unroll
        for (int j = 0; j < NI; j++) {
            int row = m0 + warp_m + i * 16 + (lane >> 2);
            int col = n0 + warp_n + j * 8 + 2 * (lane & 3);
#pragma unroll
            for (int q = 0; q < 4; q++) {
                int gr = row + (q >> 1) * 8;
                int gc = col + (q & 1);
                if (gc < N) {
                    float r = acc[i][j][q];
                    if (bias) r += bias[gc];
                    C[(size_t)gr * N + gc] = r;
                }
            }
        }
}

// ---------------- pointwise / reduction kernels -----------------------------
__global__ void softmax_kernel(float* __restrict__ attn_out)
{
    __shared__ float sm[Sq];
    int b = blockIdx.x, t = threadIdx.x;
    float x = 0.f;
#pragma unroll
    for (int q = 0; q < NSLOT; q++)
        x += g_spart[(size_t)q * SBq + t * Bq + b];
    sm[t] = x; __syncthreads();
    for (int o = 64; o > 0; o >>= 1) {
        if (t < o) sm[t] = fmaxf(sm[t], sm[t + o]);
        __syncthreads();
    }
    float m = sm[0];
    __syncthreads();
    float e = expf(x - m);
    sm[t] = e; __syncthreads();
    for (int o = 64; o > 0; o >>= 1) {
        if (t < o) sm[t] += sm[t + o];
        __syncthreads();
    }
    attn_out[b * Sq + t] = e / sm[0];
}

// context[b][h4] (float4): one block per batch row b (256 threads = H/4)
__global__ void context_kernel(const float* __restrict__ attn,
                               const float* __restrict__ enc)
{
    __shared__ float aw[Sq];
    int b = blockIdx.x;
    int h4 = threadIdx.x;               // 0..255 (float4 index)
    if (h4 < Sq) aw[h4] = attn[b * Sq + h4];
    __syncthreads();
    const float4* enc4 = reinterpret_cast<const float4*>(enc);
    float4 acc = make_float4(0.f, 0.f, 0.f, 0.f);
#pragma unroll 8
    for (int s = 0; s < Sq; s++) {
        float4 e = enc4[(size_t)(s * Bq + b) * (Hq / 4) + h4];
        float a = aw[s];
        acc.x = fmaf(a, e.x, acc.x);
        acc.y = fmaf(a, e.y, acc.y);
        acc.z = fmaf(a, e.z, acc.z);
        acc.w = fmaf(a, e.w, acc.w);
    }
    reinterpret_cast<float4*>(g_ctx)[b * (Hq / 4) + h4] = acc;
}

__global__ void xbuild_kernel(const int* __restrict__ seq,
                              const float* __restrict__ emb)
{
    int idx = blockIdx.x * 256 + threadIdx.x;
    int b = idx / KIq;
    int j = idx - b * KIq;
    float val;
    if (j < Eq) val = emb[(size_t)seq[b] * Eq + j];
    else        val = g_ctx[b * Hq + (j - Eq)];
    g_x[idx] = val;
}

__device__ __forceinline__ float sigf(float x) { return 1.f / (1.f + expf(-x)); }

__global__ void lstm_kernel(const float* __restrict__ c0,
                            float* __restrict__ h_new,
                            float* __restrict__ c_new)
{
    int idx = blockIdx.x * 256 + threadIdx.x;
    int b = idx >> 10;
    int h = idx & (Hq - 1);
    const float* g = g_gates + ((size_t)b << 12);
    float vi = g[h];
    float vf = g[Hq + h];
    float vg = g[2 * Hq + h];
    float vo = g[3 * Hq + h];
    float c = sigf(vf) * c0[idx] + sigf(vi) * tanhf(vg);
    c_new[idx] = c;
    h_new[idx] = sigf(vo) * tanhf(c);
}

__device__ __forceinline__ float blk_red_max(float v, float* red)
{
    int t = threadIdx.x;
#pragma unroll
    for (int o = 16; o > 0; o >>= 1) v = fmaxf(v, __shfl_xor_sync(~0u, v, o));
    if ((t & 31) == 0) red[t >> 5] = v;
    __syncthreads();
    if (t < 32) {
        v = red[t];
#pragma unroll
        for (int o = 16; o > 0; o >>= 1) v = fmaxf(v, __shfl_xor_sync(~0u, v, o));
        if (t == 0) red[0] = v;
    }
    __syncthreads();
    float r = red[0];
    __syncthreads();
    return r;
}

__device__ __forceinline__ float blk_red_sum(float v, float* red)
{
    int t = threadIdx.x;
#pragma unroll
    for (int o = 16; o > 0; o >>= 1) v += __shfl_xor_sync(~0u, v, o);
    if ((t & 31) == 0) red[t >> 5] = v;
    __syncthreads();
    if (t < 32) {
        v = red[t];
#pragma unroll
        for (int o = 16; o > 0; o >>= 1) v += __shfl_xor_sync(~0u, v, o);
        if (t == 0) red[0] = v;
    }
    __syncthreads();
    float r = red[0];
    __syncthreads();
    return r;
}

__global__ void logsoftmax_kernel(float* __restrict__ out)
{
    __shared__ float red[32];
    int b = blockIdx.x;
    float* row = out + (size_t)b * Vq;
    int t = threadIdx.x;

    float m = -1e30f;
    for (int j = t; j < Vq; j += 1024) m = fmaxf(m, row[j]);
    m = blk_red_max(m, red);

    float s = 0.f;
    for (int j = t; j < Vq; j += 1024) s += expf(row[j] - m);
    s = blk_red_sum(s, red);

    float lse = m + logf(s);
    for (int j = t; j < Vq; j += 1024) row[j] -= lse;
}

// ---------------------------------------------------------------------------
extern "C" void kernel_launch(void* const* d_in, const int* in_sizes, int n_in,
                              void* d_out, int out_size)
{
    const int*   seq     = (const int*)d_in[0];
    const float* h0      = (const float*)d_in[1];
    const float* c0      = (const float*)d_in[2];
    const float* enc     = (const float*)d_in[3];
    const float* emb     = (const float*)d_in[4];
    const float* W_ih    = (const float*)d_in[5];
    const float* W_hh    = (const float*)d_in[6];
    const float* b_ih    = (const float*)d_in[7];
    const float* b_hh    = (const float*)d_in[8];
    const float* attn_W  = (const float*)d_in[9];
    const float* attn_Wb = (const float*)d_in[10];
    const float* attn_U  = (const float*)d_in[11];
    const float* attn_Ub = (const float*)d_in[12];
    const float* attn_v  = (const float*)d_in[13];
    const float* out_W   = (const float*)d_in[14];
    const float* out_b   = (const float*)d_in[15];

    float* out      = (float*)d_out;
    float* o_logits = out;                          // [B, V]
    float* o_h      = out + (size_t)Bq * Vq;        // [1, B, H]
    float* o_c      = o_h + Bq * Hq;                // [1, B, H]
    float* o_attn   = o_c + Bq * Hq;                // [B, 1, S]

    float *hW, *x, *gates;
    cudaGetSymbolAddress((void**)&hW,    g_hW);
    cudaGetSymbolAddress((void**)&x,     g_x);
    cudaGetSymbolAddress((void**)&gates, g_gates);

    cudaFuncSetAttribute(tgemm_score_kernel,
                         cudaFuncAttributeMaxDynamicSharedMemorySize, T_SMEM);

    // 1) hW = h0 @ attn_W^T + attn_Wb  [64,1024] (3xBF16), split into 3
    //    launches so the T kernel lands at ncu's captured launch index 3.
    mma3bf_gemm_nt<64, 128, 32, 32, 32><<<dim3(3, 1), 256>>>(
        h0, attn_W, hW, Bq, Hq, Hq, attn_Wb, 0, 0);
    mma3bf_gemm_nt<64, 128, 32, 32, 32><<<dim3(3, 1), 256>>>(
        h0, attn_W, hW, Bq, Hq, Hq, attn_Wb, 0, 384);
    mma3bf_gemm_nt<64, 128, 32, 32, 32><<<dim3(2, 1), 256>>>(
        h0, attn_W, hW, Bq, Hq, Hq, attn_Wb, 0, 768);

    // 2) fused energy GEMM (3xBF16, double-buffered) + score partials
    tgemm_score_kernel<<<dim3(Hq / 64, SBq / 128), 256, T_SMEM>>>(
        enc, attn_U, attn_Ub, attn_v);

    // 3) attn = softmax(reduce(spart)) -> output region
    softmax_kernel<<<Bq, Sq>>>(o_attn);

    // 4) context = attn @ enc  (float4, one block per b)
    context_kernel<<<Bq, Hq / 4>>>(o_attn, enc);

    // 5) x = [emb[seq] ; context]                [64, 1536]
    xbuild_kernel<<<Bq * KIq / 256, 256>>>(seq, emb);

    // 6) gates  = x @ W_ih^T + b_ih              [64, 4096]   (3xBF16)
    mma3bf_gemm_nt<64, 128, 32, 32, 32><<<dim3(G4q / 128, 1), 256>>>(
        x, W_ih, gates, Bq, G4q, KIq, b_ih, 0, 0);

    // 7) gates += h0 @ W_hh^T + b_hh                          (3xBF16)
    mma3bf_gemm_nt<64, 128, 32, 32, 32><<<dim3(G4q / 128, 1), 256>>>(
        h0, W_hh, gates, Bq, G4q, Hq, b_hh, 1, 0);

    // 8) LSTM pointwise -> h_new, c_new in output
    lstm_kernel<<<Bq * Hq / 256, 256>>>(c0, o_h, o_c);

    // 9) logits = h_new @ out_W^T + out_b        [64, 50257]  (single tf32)
    mma_gemm_nt<64, 128, 32, 32, 32><<<dim3((Vq + 127) / 128, 1), 256>>>(
        o_h, out_W, o_logits, Bq, Vq, Hq, out_b);

    // 10) in-place log_softmax over V
    logsoftmax_kernel<<<Bq, 1024>>>(o_logits);
}

// round 10
// speedup vs baseline: 1.3210x; 1.3210x over previous
#include <cuda_runtime.h>
#include <cuda_bf16.h>
#include <math.h>
#include <stdint.h>

#define Bq 64
#define Sq 128
#define Eq 512
#define Hq 1024
#define Vq 50257
#define KIq (Eq + Hq)   /* 1536 */
#define G4q (4 * Hq)    /* 4096 */
#define SBq (Sq * Bq)   /* 8192 */
#define NSLOT 32

// ---------------- scratch (static device globals; no runtime allocation) ----
__device__ float g_hW[Bq * Hq];
__device__ float g_spart[NSLOT * SBq];  // score column-partials per (s,b) row
__device__ float g_ctx[Bq * Hq];
__device__ float g_x[Bq * KIq];
__device__ float g_gates[Bq * G4q];

// ---------------- helpers ---------------------------------------------------
__device__ __forceinline__ uint32_t smem_u32(const void* p)
{
    uint32_t a;
    asm("{ .reg .u64 t; cvta.to.shared.u64 t, %1; cvt.u32.u64 %0, t; }"
        : "=r"(a) : "l"(p));
    return a;
}

__device__ __forceinline__ void split_bf16(float x, float& hi, float& lo)
{
    hi = __bfloat162float(__float2bfloat16(x));
    lo = x - hi;
}

// pack two floats as bf16x2: low 16 bits = e0, high = e1
__device__ __forceinline__ unsigned pack2(float e0, float e1)
{
    unsigned r;
    asm("cvt.rn.bf16x2.f32 %0, %1, %2;" : "=r"(r) : "f"(e1), "f"(e0));
    return r;
}

__device__ __forceinline__ void mma_bf16(float c[4], const unsigned a[4],
                                         const unsigned b[2])
{
    asm volatile(
        "mma.sync.aligned.m16n8k16.row.col.f32.bf16.bf16.f32 "
        "{%0,%1,%2,%3}, {%4,%5,%6,%7}, {%8,%9}, {%0,%1,%2,%3};"
        : "+f"(c[0]), "+f"(c[1]), "+f"(c[2]), "+f"(c[3])
        : "r"(a[0]), "r"(a[1]), "r"(a[2]), "r"(a[3]), "r"(b[0]), "r"(b[1]));
}

__device__ __forceinline__ void mma_tf32(float c[4], const unsigned a[4],
                                         const unsigned b[2])
{
    asm volatile(
        "mma.sync.aligned.m16n8k8.row.col.f32.tf32.tf32.f32 "
        "{%0,%1,%2,%3}, {%4,%5,%6,%7}, {%8,%9}, {%0,%1,%2,%3};"
        : "+f"(c[0]), "+f"(c[1]), "+f"(c[2]), "+f"(c[3])
        : "r"(a[0]), "r"(a[1]), "r"(a[2]), "r"(a[3]), "r"(b[0]), "r"(b[1]));
}

__device__ __forceinline__ float tanh_fast(float x)
{
    float cx = fminf(fmaxf(x, -15.f), 15.f);
    float e = __expf(2.f * cx);
    return __fdividef(e - 1.f, e + 1.f);
}

// cp.async 16B, L2-only (.cg). src_ok=0 zero-fills.
__device__ __forceinline__ void cp16(uint32_t dst, const void* src, int src_ok)
{
    asm volatile("cp.async.cg.shared.global [%0], [%1], 16, %2;"
                 :: "r"(dst), "l"(src), "r"(src_ok ? 16 : 0) : "memory");
}
__device__ __forceinline__ void cp_commit()
{
    asm volatile("cp.async.commit_group;" ::: "memory");
}
template <int N>
__device__ __forceinline__ void cp_wait()
{
    asm volatile("cp.async.wait_group %0;" :: "n"(N) : "memory");
}

// ================== 3xBF16 GEMM template (hi/lo compensated) ================
// C[M,N] = A[M,K] @ B[N,K]^T (+bias)(+=C). M%BM==0, K%BK==0, N ragged.
template <int BM, int BN, int BK, int WM, int WN>
__global__ void __launch_bounds__(256)
mma3bf_gemm_nt(const float* __restrict__ A, const float* __restrict__ Bm,
               float* __restrict__ C, int M, int N, int K,
               const float* __restrict__ bias, int accum)
{
    constexpr int MI = WM / 16;
    constexpr int NI = WN / 8;
    constexpr int PP = BK / 2;          // pairs per row
    constexpr int KPP = PP + 4;         // padded pairs
    constexpr int F4R = BK / 4;         // float4 loads per row
    constexpr int RPP = 256 / F4R;

    __shared__ unsigned Ah[BM][KPP], Al[BM][KPP];
    __shared__ unsigned Bh[BN][KPP], Bl[BN][KPP];

    const int tid = threadIdx.x;
    const int lane = tid & 31;
    const int w = tid >> 5;
    const int warp_m = (w % (BM / WM)) * WM;
    const int warp_n = (w / (BM / WM)) * WN;
    const int m0 = blockIdx.y * BM;
    const int n0 = blockIdx.x * BN;
    const int lrow = tid / F4R;
    const int lk4 = (tid % F4R) * 4;    // float offset
    const int lp = lk4 >> 1;            // pair offset

    float acc[MI][NI][4];
#pragma unroll
    for (int i = 0; i < MI; i++)
#pragma unroll
        for (int j = 0; j < NI; j++)
#pragma unroll
            for (int q = 0; q < 4; q++) acc[i][j][q] = 0.f;

    for (int k0 = 0; k0 < K; k0 += BK) {
#pragma unroll
        for (int r = lrow; r < BM; r += RPP) {
            float4 vv = *reinterpret_cast<const float4*>(
                A + (size_t)(m0 + r) * K + k0 + lk4);
            float hx, lx, hy, ly, hz, lz, hw, lw;
            split_bf16(vv.x, hx, lx); split_bf16(vv.y, hy, ly);
            split_bf16(vv.z, hz, lz); split_bf16(vv.w, hw, lw);
            Ah[r][lp] = pack2(hx, hy); Ah[r][lp + 1] = pack2(hz, hw);
            Al[r][lp] = pack2(lx, ly); Al[r][lp + 1] = pack2(lz, lw);
        }
#pragma unroll
        for (int r = lrow; r < BN; r += RPP) {
            float4 vv = make_float4(0.f, 0.f, 0.f, 0.f);
            if (n0 + r < N)
                vv = *reinterpret_cast<const float4*>(
                    Bm + (size_t)(n0 + r) * K + k0 + lk4);
            float hx, lx, hy, ly, hz, lz, hw, lw;
            split_bf16(vv.x, hx, lx); split_bf16(vv.y, hy, ly);
            split_bf16(vv.z, hz, lz); split_bf16(vv.w, hw, lw);
            Bh[r][lp] = pack2(hx, hy); Bh[r][lp + 1] = pack2(hz, hw);
            Bl[r][lp] = pack2(lx, ly); Bl[r][lp + 1] = pack2(lz, lw);
        }
        __syncthreads();

#pragma unroll
        for (int kk = 0; kk < PP; kk += 8) {
            unsigned ah[MI][4], al[MI][4], bh[NI][2], bl[NI][2];
#pragma unroll
            for (int i = 0; i < MI; i++) {
                int r = warp_m + i * 16 + (lane >> 2);
                int cb = kk + (lane & 3);
                ah[i][0] = Ah[r][cb];     ah[i][1] = Ah[r + 8][cb];
                ah[i][2] = Ah[r][cb + 4]; ah[i][3] = Ah[r + 8][cb + 4];
                al[i][0] = Al[r][cb];     al[i][1] = Al[r + 8][cb];
                al[i][2] = Al[r][cb + 4]; al[i][3] = Al[r + 8][cb + 4];
            }
#pragma unroll
            for (int j = 0; j < NI; j++) {
                int r = warp_n + j * 8 + (lane >> 2);
                int cb = kk + (lane & 3);
                bh[j][0] = Bh[r][cb]; bh[j][1] = Bh[r][cb + 4];
                bl[j][0] = Bl[r][cb]; bl[j][1] = Bl[r][cb + 4];
            }
#pragma unroll
            for (int i = 0; i < MI; i++)
#pragma unroll
                for (int j = 0; j < NI; j++) {
                    mma_bf16(acc[i][j], ah[i], bl[j]);
                    mma_bf16(acc[i][j], al[i], bh[j]);
                    mma_bf16(acc[i][j], ah[i], bh[j]);
                }
        }
        __syncthreads();
    }

#pragma unroll
    for (int i = 0; i < MI; i++)
#pragma unroll
        for (int j = 0; j < NI; j++) {
            int row = m0 + warp_m + i * 16 + (lane >> 2);
            int col = n0 + warp_n + j * 8 + 2 * (lane & 3);
#pragma unroll
            for (int q = 0; q < 4; q++) {
                int gr = row + (q >> 1) * 8;
                int gc = col + (q & 1);
                if (gc < N) {
                    float r = acc[i][j][q];
                    if (bias) r += bias[gc];
                    size_t off = (size_t)gr * N + gc;
                    if (accum) r += C[off];
                    C[off] = r;
                }
            }
        }
}

// ============ 3xBF16 energy GEMM + fused score epilogue (R8 version) ========
// T = enc[8192,1024] @ U[1024,1024]^T; epilogue: partial score
// sum_cols v * tanh(T + Ub + hW) per row, 32 deterministic slots.
// BM=128, BN=64, BK=32; warp grid 4(M)x2(N), warp tile 32x32 (MI=2, NI=4).
__global__ void __launch_bounds__(256, 2)
tgemm_score_kernel(const float* __restrict__ enc, const float* __restrict__ U,
                   const float* __restrict__ Ub, const float* __restrict__ v)
{
    constexpr int BM = 128, BN = 64, BK = 32;
    constexpr int MI = 2;               // WM=32
    constexpr int NI = 4;               // WN=32
    constexpr int PP = BK / 2;          // 16
    constexpr int KPP = PP + 4;         // 20
    constexpr int F4R = BK / 4;         // 8
    constexpr int RPP = 256 / F4R;      // 32

    __shared__ unsigned Ah[BM][KPP], Al[BM][KPP];
    __shared__ unsigned Bh[BN][KPP], Bl[BN][KPP];

    const int tid = threadIdx.x;
    const int lane = tid & 31;
    const int w = tid >> 5;
    const int lane4 = lane >> 2;
    const int lanek = lane & 3;
    const int warp_m = (w & 3) * 32;    // 4 warps along M
    const int warp_n = (w >> 2) * 32;   // 2 warps along N
    const int m0 = blockIdx.y * BM;
    const int n0 = blockIdx.x * BN;
    const int lrow = tid / F4R;
    const int lk4 = (tid % F4R) * 4;
    const int lp = lk4 >> 1;

    float acc[MI][NI][4];
#pragma unroll
    for (int i = 0; i < MI; i++)
#pragma unroll
        for (int j = 0; j < NI; j++)
#pragma unroll
            for (int q = 0; q < 4; q++) acc[i][j][q] = 0.f;

    for (int k0 = 0; k0 < Hq; k0 += BK) {
#pragma unroll
        for (int r = lrow; r < BM; r += RPP) {
            float4 vv = *reinterpret_cast<const float4*>(
                enc + (size_t)(m0 + r) * Hq + k0 + lk4);
            float hx, lx, hy, ly, hz, lz, hw, lw;
            split_bf16(vv.x, hx, lx); split_bf16(vv.y, hy, ly);
            split_bf16(vv.z, hz, lz); split_bf16(vv.w, hw, lw);
            Ah[r][lp] = pack2(hx, hy); Ah[r][lp + 1] = pack2(hz, hw);
            Al[r][lp] = pack2(lx, ly); Al[r][lp + 1] = pack2(lz, lw);
        }
#pragma unroll
        for (int r = lrow; r < BN; r += RPP) {
            float4 vv = *reinterpret_cast<const float4*>(
                U + (size_t)(n0 + r) * Hq + k0 + lk4);
            float hx, lx, hy, ly, hz, lz, hw, lw;
            split_bf16(vv.x, hx, lx); split_bf16(vv.y, hy, ly);
            split_bf16(vv.z, hz, lz); split_bf16(vv.w, hw, lw);
            Bh[r][lp] = pack2(hx, hy); Bh[r][lp + 1] = pack2(hz, hw);
            Bl[r][lp] = pack2(lx, ly); Bl[r][lp + 1] = pack2(lz, lw);
        }
        __syncthreads();

#pragma unroll
        for (int kk = 0; kk < PP; kk += 8) {
            unsigned ah[MI][4], al[MI][4], bh[NI][2], bl[NI][2];
#pragma unroll
            for (int i = 0; i < MI; i++) {
                int r = warp_m + i * 16 + lane4;
                int cb = kk + lanek;
                ah[i][0] = Ah[r][cb];     ah[i][1] = Ah[r + 8][cb];
                ah[i][2] = Ah[r][cb + 4]; ah[i][3] = Ah[r + 8][cb + 4];
                al[i][0] = Al[r][cb];     al[i][1] = Al[r + 8][cb];
                al[i][2] = Al[r][cb + 4]; al[i][3] = Al[r + 8][cb + 4];
            }
#pragma unroll
            for (int j = 0; j < NI; j++) {
                int r = warp_n + j * 8 + lane4;
                int cb = kk + lanek;
                bh[j][0] = Bh[r][cb]; bh[j][1] = Bh[r][cb + 4];
                bl[j][0] = Bl[r][cb]; bl[j][1] = Bl[r][cb + 4];
            }
#pragma unroll
            for (int i = 0; i < MI; i++)
#pragma unroll
                for (int j = 0; j < NI; j++) {
                    mma_bf16(acc[i][j], ah[i], bl[j]);
                    mma_bf16(acc[i][j], al[i], bh[j]);
                    mma_bf16(acc[i][j], ah[i], bh[j]);
                }
        }
        __syncthreads();
    }

    // ---- fused score epilogue over this warp's 32 columns ------------------
    float vv[NI][2], uu[NI][2];
#pragma unroll
    for (int j = 0; j < NI; j++)
#pragma unroll
        for (int qc = 0; qc < 2; qc++) {
            int c = n0 + warp_n + j * 8 + 2 * lanek + qc;
            vv[j][qc] = v[c];
            uu[j][qc] = Ub[c];
        }

    const int slot = blockIdx.x * 2 + (w >> 2);   // 16 blocks x 2 n-warps = 32
#pragma unroll
    for (int i = 0; i < MI; i++)
#pragma unroll
        for (int qr = 0; qr < 2; qr++) {
            int row = m0 + warp_m + i * 16 + lane4 + qr * 8;
            int b = row & (Bq - 1);
            const float* hwr = g_hW + (size_t)b * Hq + n0 + warp_n + 2 * lanek;
            float part = 0.f;
#pragma unroll
            for (int j = 0; j < NI; j++)
#pragma unroll
                for (int qc = 0; qc < 2; qc++) {
                    float t = acc[i][j][2 * qr + qc] + uu[j][qc]
                              + hwr[j * 8 + qc];
                    part += vv[j][qc] * tanh_fast(t);
                }
            part += __shfl_xor_sync(0xffffffffu, part, 1);
            part += __shfl_xor_sync(0xffffffffu, part, 2);
            if (lanek == 0)
                g_spart[(size_t)slot * SBq + row] = part;
        }
}

// ====== logits GEMM: cp.async 4-stage pipelined, raw-tf32 (truncation) ======
// C[64, V] = h[64,1024] @ out_W[V,1024]^T + out_b. BM=64, BN=128, BK=32.
// Raw fp32 bits feed mma.tf32 directly (truncation ~2^-10, fine vs 1e-3).
#define LG_STAGES 4
#define LG_KP 36                        /* padded row, units of 4B */
#define LG_AOFF 0                       /* A: 64 rows */
#define LG_BOFF (64 * LG_KP)            /* B: 128 rows */
#define LG_STG ((64 + 128) * LG_KP)     /* u32 per stage = 6912 */
#define LG_SMEM (LG_STAGES * LG_STG * 4)   /* 110592 B */

__global__ void __launch_bounds__(256)
logits_kernel(const float* __restrict__ A, const float* __restrict__ Bm,
              float* __restrict__ C, const float* __restrict__ bias)
{
    extern __shared__ unsigned sml[];
    constexpr int MI = 2, NI = 4;       // WM=32, WN=32; warp grid 2(M)x4(N)
    const int N = Vq, K = Hq;

    const int tid = threadIdx.x;
    const int lane = tid & 31;
    const int w = tid >> 5;
    const int warp_m = (w & 1) * 32;
    const int warp_n = (w >> 1) * 32;
    const int n0 = blockIdx.x * 128;
    const int lrow = tid >> 3;          // 0..31
    const int lk4 = (tid & 7) * 4;      // float offset in row

    // per-thread cp.async assignments:
    // A: rows lrow, lrow+32 (64 rows); B: rows lrow..lrow+96 step 32 (128 rows)
    const float* Abase = A + (size_t)lrow * K + lk4;
    const float* Bbase = Bm + (size_t)(n0 + lrow) * K + lk4;

    float acc[MI][NI][4];
#pragma unroll
    for (int i = 0; i < MI; i++)
#pragma unroll
        for (int j = 0; j < NI; j++)
#pragma unroll
            for (int q = 0; q < 4; q++) acc[i][j][q] = 0.f;

    auto issue = [&](int ch) {
        unsigned* st = sml + (ch & (LG_STAGES - 1)) * LG_STG;
        int k0 = ch * 32;
        uint32_t abase = smem_u32(st);
#pragma unroll
        for (int u = 0; u < 2; u++) {
            int r = lrow + u * 32;
            cp16(abase + (LG_AOFF + r * LG_KP + lk4) * 4,
                 Abase + (size_t)u * 32 * K + k0, 1);
        }
#pragma unroll
        for (int u = 0; u < 4; u++) {
            int r = lrow + u * 32;
            cp16(abase + (LG_BOFF + r * LG_KP + lk4) * 4,
                 Bbase + (size_t)u * 32 * K + k0, (n0 + r) < N);
        }
        cp_commit();
    };

    issue(0); issue(1); issue(2);

    for (int ch = 0; ch < 32; ch++) {
        cp_wait<2>();
        __syncthreads();
        const unsigned* st = sml + (ch & (LG_STAGES - 1)) * LG_STG;

#pragma unroll
        for (int kk = 0; kk < 32; kk += 8) {
            unsigned af[MI][4], bf[NI][2];
#pragma unroll
            for (int i = 0; i < MI; i++) {
                int r = warp_m + i * 16 + (lane >> 2);
                int cb = kk + (lane & 3);
                af[i][0] = st[LG_AOFF + r * LG_KP + cb];
                af[i][1] = st[LG_AOFF + (r + 8) * LG_KP + cb];
                af[i][2] = st[LG_AOFF + r * LG_KP + cb + 4];
                af[i][3] = st[LG_AOFF + (r + 8) * LG_KP + cb + 4];
            }
#pragma unroll
            for (int j = 0; j < NI; j++) {
                int r = warp_n + j * 8 + (lane >> 2);
                int cb = kk + (lane & 3);
                bf[j][0] = st[LG_BOFF + r * LG_KP + cb];
                bf[j][1] = st[LG_BOFF + r * LG_KP + cb + 4];
            }
#pragma unroll
            for (int i = 0; i < MI; i++)
#pragma unroll
                for (int j = 0; j < NI; j++)
                    mma_tf32(acc[i][j], af[i], bf[j]);
        }

        if (ch + 3 < 32) issue(ch + 3);
        else cp_commit();               // keep group count consistent
    }

#pragma unroll
    for (int i = 0; i < MI; i++)
#pragma unroll
        for (int j = 0; j < NI; j++) {
            int row = warp_m + i * 16 + (lane >> 2);
            int col = n0 + warp_n + j * 8 + 2 * (lane & 3);
#pragma unroll
            for (int q = 0; q < 4; q++) {
                int gr = row + (q >> 1) * 8;
                int gc = col + (q & 1);
                if (gc < N)
                    C[(size_t)gr * N + gc] = acc[i][j][q] + bias[gc];
            }
        }
}

// ---------------- pointwise / reduction kernels -----------------------------
__global__ void softmax_kernel(float* __restrict__ attn_out)
{
    __shared__ float sm[Sq];
    int b = blockIdx.x, t = threadIdx.x;
    float x = 0.f;
#pragma unroll
    for (int q = 0; q < NSLOT; q++)
        x += g_spart[(size_t)q * SBq + t * Bq + b];
    sm[t] = x; __syncthreads();
    for (int o = 64; o > 0; o >>= 1) {
        if (t < o) sm[t] = fmaxf(sm[t], sm[t + o]);
        __syncthreads();
    }
    float m = sm[0];
    __syncthreads();
    float e = expf(x - m);
    sm[t] = e; __syncthreads();
    for (int o = 64; o > 0; o >>= 1) {
        if (t < o) sm[t] += sm[t + o];
        __syncthreads();
    }
    attn_out[b * Sq + t] = e / sm[0];
}

__global__ void context_kernel(const float* __restrict__ attn,
                               const float* __restrict__ enc)
{
    __shared__ float aw[Sq];
    int idx = blockIdx.x * 256 + threadIdx.x;
    int b = idx >> 10;
    int h = idx & (Hq - 1);
    if (threadIdx.x < Sq) aw[threadIdx.x] = attn[b * Sq + threadIdx.x];
    __syncthreads();
    float acc = 0.f;
#pragma unroll 4
    for (int s = 0; s < Sq; s++)
        acc = fmaf(aw[s], enc[((size_t)s * Bq + b) * Hq + h], acc);
    g_ctx[idx] = acc;
}

__global__ void xbuild_kernel(const int* __restrict__ seq,
                              const float* __restrict__ emb)
{
    int idx = blockIdx.x * 256 + threadIdx.x;
    int b = idx / KIq;
    int j = idx - b * KIq;
    float val;
    if (j < Eq) val = emb[(size_t)seq[b] * Eq + j];
    else        val = g_ctx[b * Hq + (j - Eq)];
    g_x[idx] = val;
}

__device__ __forceinline__ float sigf(float x) { return 1.f / (1.f + expf(-x)); }

__global__ void lstm_kernel(const float* __restrict__ c0,
                            float* __restrict__ h_new,
                            float* __restrict__ c_new)
{
    int idx = blockIdx.x * 256 + threadIdx.x;
    int b = idx >> 10;
    int h = idx & (Hq - 1);
    const float* g = g_gates + ((size_t)b << 12);
    float vi = g[h];
    float vf = g[Hq + h];
    float vg = g[2 * Hq + h];
    float vo = g[3 * Hq + h];
    float c = sigf(vf) * c0[idx] + sigf(vi) * tanhf(vg);
    c_new[idx] = c;
    h_new[idx] = sigf(vo) * tanhf(c);
}

__device__ __forceinline__ float blk_red_max(float v, float* red)
{
    int t = threadIdx.x;
#pragma unroll
    for (int o = 16; o > 0; o >>= 1) v = fmaxf(v, __shfl_xor_sync(~0u, v, o));
    if ((t & 31) == 0) red[t >> 5] = v;
    __syncthreads();
    if (t < 32) {
        v = red[t];
#pragma unroll
        for (int o = 16; o > 0; o >>= 1) v = fmaxf(v, __shfl_xor_sync(~0u, v, o));
        if (t == 0) red[0] = v;
    }
    __syncthreads();
    float r = red[0];
    __syncthreads();
    return r;
}

__device__ __forceinline__ float blk_red_sum(float v, float* red)
{
    int t = threadIdx.x;
#pragma unroll
    for (int o = 16; o > 0; o >>= 1) v += __shfl_xor_sync(~0u, v, o);
    if ((t & 31) == 0) red[t >> 5] = v;
    __syncthreads();
    if (t < 32) {
        v = red[t];
#pragma unroll
        for (int o = 16; o > 0; o >>= 1) v += __shfl_xor_sync(~0u, v, o);
        if (t == 0) red[0] = v;
    }
    __syncthreads();
    float r = red[0];
    __syncthreads();
    return r;
}

__global__ void logsoftmax_kernel(float* __restrict__ out)
{
    __shared__ float red[32];
    int b = blockIdx.x;
    float* row = out + (size_t)b * Vq;
    int t = threadIdx.x;

    float m = -1e30f;
    for (int j = t; j < Vq; j += 1024) m = fmaxf(m, row[j]);
    m = blk_red_max(m, red);

    float s = 0.f;
    for (int j = t; j < Vq; j += 1024) s += expf(row[j] - m);
    s = blk_red_sum(s, red);

    float lse = m + logf(s);
    for (int j = t; j < Vq; j += 1024) row[j] -= lse;
}

// ---------------------------------------------------------------------------
extern "C" void kernel_launch(void* const* d_in, const int* in_sizes, int n_in,
                              void* d_out, int out_size)
{
    const int*   seq     = (const int*)d_in[0];
    const float* h0      = (const float*)d_in[1];
    const float* c0      = (const float*)d_in[2];
    const float* enc     = (const float*)d_in[3];
    const float* emb     = (const float*)d_in[4];
    const float* W_ih    = (const float*)d_in[5];
    const float* W_hh    = (const float*)d_in[6];
    const float* b_ih    = (const float*)d_in[7];
    const float* b_hh    = (const float*)d_in[8];
    const float* attn_W  = (const float*)d_in[9];
    const float* attn_Wb = (const float*)d_in[10];
    const float* attn_U  = (const float*)d_in[11];
    const float* attn_Ub = (const float*)d_in[12];
    const float* attn_v  = (const float*)d_in[13];
    const float* out_W   = (const float*)d_in[14];
    const float* out_b   = (const float*)d_in[15];

    float* out      = (float*)d_out;
    float* o_logits = out;                          // [B, V]
    float* o_h      = out + (size_t)Bq * Vq;        // [1, B, H]
    float* o_c      = o_h + Bq * Hq;                // [1, B, H]
    float* o_attn   = o_c + Bq * Hq;                // [B, 1, S]

    float *hW, *x, *gates;
    cudaGetSymbolAddress((void**)&hW,    g_hW);
    cudaGetSymbolAddress((void**)&x,     g_x);
    cudaGetSymbolAddress((void**)&gates, g_gates);

    cudaFuncSetAttribute(logits_kernel,
                         cudaFuncAttributeMaxDynamicSharedMemorySize, LG_SMEM);

    // 1) hW = h0 @ attn_W^T + attn_Wb            [64, 1024]   (3xBF16)
    mma3bf_gemm_nt<64, 128, 32, 32, 32><<<dim3(Hq / 128, 1), 256>>>(
        h0, attn_W, hW, Bq, Hq, Hq, attn_Wb, 0);

    // 2) fused energy GEMM (3xBF16, BN=64 tile) + score partials
    tgemm_score_kernel<<<dim3(Hq / 64, SBq / 128), 256>>>(
        enc, attn_U, attn_Ub, attn_v);

    // 3) attn = softmax(reduce(spart)) -> output region
    softmax_kernel<<<Bq, Sq>>>(o_attn);

    // 4) context = attn @ enc                    [64, 1024]
    context_kernel<<<Bq * Hq / 256, 256>>>(o_attn, enc);

    // 5) x = [emb[seq] ; context]                [64, 1536]
    xbuild_kernel<<<Bq * KIq / 256, 256>>>(seq, emb);

    // 6) gates  = x @ W_ih^T + b_ih              [64, 4096]   (3xBF16)
    mma3bf_gemm_nt<64, 128, 32, 32, 32><<<dim3(G4q / 128, 1), 256>>>(
        x, W_ih, gates, Bq, G4q, KIq, b_ih, 0);

    // 7) gates += h0 @ W_hh^T + b_hh                          (3xBF16)
    mma3bf_gemm_nt<64, 128, 32, 32, 32><<<dim3(G4q / 128, 1), 256>>>(
        h0, W_hh, gates, Bq, G4q, Hq, b_hh, 1);

    // 8) LSTM pointwise -> h_new, c_new in output
    lstm_kernel<<<Bq * Hq / 256, 256>>>(c0, o_h, o_c);

    // 9) logits = h_new @ out_W^T + out_b  [64, 50257]  (cp.async tf32)
    logits_kernel<<<dim3((Vq + 127) / 128, 1), 256, LG_SMEM>>>(
        o_h, out_W, o_logits, out_b);

    // 10) in-place log_softmax over V
    logsoftmax_kernel<<<Bq, 1024>>>(o_logits);
}

// round 11
// speedup vs baseline: 1.3641x; 1.0327x over previous
#include <cuda_runtime.h>
#include <cuda_bf16.h>
#include <math.h>
#include <stdint.h>

#define Bq 64
#define Sq 128
#define Eq 512
#define Hq 1024
#define Vq 50257
#define KIq (Eq + Hq)   /* 1536 */
#define G4q (4 * Hq)    /* 4096 */
#define SBq (Sq * Bq)   /* 8192 */
#define NSLOT 32

// ---------------- scratch (static device globals; no runtime allocation) ----
__device__ float g_hW[Bq * Hq];
__device__ float g_spart[NSLOT * SBq];  // score column-partials per (s,b) row
__device__ float g_ctx[Bq * Hq];
__device__ float g_x[Bq * KIq];
__device__ float g_gates[Bq * G4q];

// ---------------- helpers ---------------------------------------------------
__device__ __forceinline__ uint32_t smem_u32(const void* p)
{
    uint32_t a;
    asm("{ .reg .u64 t; cvta.to.shared.u64 t, %1; cvt.u32.u64 %0, t; }"
        : "=r"(a) : "l"(p));
    return a;
}

__device__ __forceinline__ void split_bf16(float x, float& hi, float& lo)
{
    hi = __bfloat162float(__float2bfloat16(x));
    lo = x - hi;
}

// pack two floats as bf16x2: low 16 bits = e0, high = e1
__device__ __forceinline__ unsigned pack2(float e0, float e1)
{
    unsigned r;
    asm("cvt.rn.bf16x2.f32 %0, %1, %2;" : "=r"(r) : "f"(e1), "f"(e0));
    return r;
}

__device__ __forceinline__ void mma_bf16(float c[4], const unsigned a[4],
                                         const unsigned b[2])
{
    asm volatile(
        "mma.sync.aligned.m16n8k16.row.col.f32.bf16.bf16.f32 "
        "{%0,%1,%2,%3}, {%4,%5,%6,%7}, {%8,%9}, {%0,%1,%2,%3};"
        : "+f"(c[0]), "+f"(c[1]), "+f"(c[2]), "+f"(c[3])
        : "r"(a[0]), "r"(a[1]), "r"(a[2]), "r"(a[3]), "r"(b[0]), "r"(b[1]));
}

__device__ __forceinline__ void mma_tf32(float c[4], const unsigned a[4],
                                         const unsigned b[2])
{
    asm volatile(
        "mma.sync.aligned.m16n8k8.row.col.f32.tf32.tf32.f32 "
        "{%0,%1,%2,%3}, {%4,%5,%6,%7}, {%8,%9}, {%0,%1,%2,%3};"
        : "+f"(c[0]), "+f"(c[1]), "+f"(c[2]), "+f"(c[3])
        : "r"(a[0]), "r"(a[1]), "r"(a[2]), "r"(a[3]), "r"(b[0]), "r"(b[1]));
}

__device__ __forceinline__ float tanh_fast(float x)
{
    float cx = fminf(fmaxf(x, -15.f), 15.f);
    float e = __expf(2.f * cx);
    return __fdividef(e - 1.f, e + 1.f);
}

// cp.async 16B, L2-only (.cg). src_ok=0 zero-fills.
__device__ __forceinline__ void cp16(uint32_t dst, const void* src, int src_ok)
{
    asm volatile("cp.async.cg.shared.global [%0], [%1], 16, %2;"
                 :: "r"(dst), "l"(src), "r"(src_ok ? 16 : 0) : "memory");
}
__device__ __forceinline__ void cp_commit()
{
    asm volatile("cp.async.commit_group;" ::: "memory");
}
template <int N>
__device__ __forceinline__ void cp_wait()
{
    asm volatile("cp.async.wait_group %0;" :: "n"(N) : "memory");
}

// ================== 3xBF16 GEMM template (hi/lo interleaved uint2) ==========
// C[M,N] = A[M,K] @ B[N,K]^T (+bias)(+=C). M%BM==0, K%BK==0, N ragged.
// Smem entry [r][p] = uint2{ hi bf16x2 pair, lo bf16x2 pair } -> one LDS.64
// fetches both compensation operands of a fragment element.
template <int BM, int BN, int BK, int WM, int WN>
__global__ void __launch_bounds__(256)
mma3bf_gemm_nt(const float* __restrict__ A, const float* __restrict__ Bm,
               float* __restrict__ C, int M, int N, int K,
               const float* __restrict__ bias, int accum)
{
    constexpr int MI = WM / 16;
    constexpr int NI = WN / 8;
    constexpr int PP = BK / 2;          // pairs per row
    constexpr int KPP = PP + 4;         // padded pairs
    constexpr int F4R = BK / 4;         // float4 loads per row
    constexpr int RPP = 256 / F4R;

    __shared__ uint2 Aa[BM][KPP];
    __shared__ uint2 Ba[BN][KPP];

    const int tid = threadIdx.x;
    const int lane = tid & 31;
    const int w = tid >> 5;
    const int warp_m = (w % (BM / WM)) * WM;
    const int warp_n = (w / (BM / WM)) * WN;
    const int m0 = blockIdx.y * BM;
    const int n0 = blockIdx.x * BN;
    const int lrow = tid / F4R;
    const int lk4 = (tid % F4R) * 4;    // float offset
    const int lp = lk4 >> 1;            // pair offset

    float acc[MI][NI][4];
#pragma unroll
    for (int i = 0; i < MI; i++)
#pragma unroll
        for (int j = 0; j < NI; j++)
#pragma unroll
            for (int q = 0; q < 4; q++) acc[i][j][q] = 0.f;

    for (int k0 = 0; k0 < K; k0 += BK) {
#pragma unroll
        for (int r = lrow; r < BM; r += RPP) {
            float4 vv = *reinterpret_cast<const float4*>(
                A + (size_t)(m0 + r) * K + k0 + lk4);
            float hx, lx, hy, ly, hz, lz, hw, lw;
            split_bf16(vv.x, hx, lx); split_bf16(vv.y, hy, ly);
            split_bf16(vv.z, hz, lz); split_bf16(vv.w, hw, lw);
            Aa[r][lp]     = make_uint2(pack2(hx, hy), pack2(lx, ly));
            Aa[r][lp + 1] = make_uint2(pack2(hz, hw), pack2(lz, lw));
        }
#pragma unroll
        for (int r = lrow; r < BN; r += RPP) {
            float4 vv = make_float4(0.f, 0.f, 0.f, 0.f);
            if (n0 + r < N)
                vv = *reinterpret_cast<const float4*>(
                    Bm + (size_t)(n0 + r) * K + k0 + lk4);
            float hx, lx, hy, ly, hz, lz, hw, lw;
            split_bf16(vv.x, hx, lx); split_bf16(vv.y, hy, ly);
            split_bf16(vv.z, hz, lz); split_bf16(vv.w, hw, lw);
            Ba[r][lp]     = make_uint2(pack2(hx, hy), pack2(lx, ly));
            Ba[r][lp + 1] = make_uint2(pack2(hz, hw), pack2(lz, lw));
        }
        __syncthreads();

#pragma unroll
        for (int kk = 0; kk < PP; kk += 8) {
            unsigned ah[MI][4], al[MI][4], bh[NI][2], bl[NI][2];
#pragma unroll
            for (int i = 0; i < MI; i++) {
                int r = warp_m + i * 16 + (lane >> 2);
                int cb = kk + (lane & 3);
                uint2 t0 = Aa[r][cb];      ah[i][0] = t0.x; al[i][0] = t0.y;
                uint2 t1 = Aa[r + 8][cb];  ah[i][1] = t1.x; al[i][1] = t1.y;
                uint2 t2 = Aa[r][cb + 4];  ah[i][2] = t2.x; al[i][2] = t2.y;
                uint2 t3 = Aa[r + 8][cb + 4]; ah[i][3] = t3.x; al[i][3] = t3.y;
            }
#pragma unroll
            for (int j = 0; j < NI; j++) {
                int r = warp_n + j * 8 + (lane >> 2);
                int cb = kk + (lane & 3);
                uint2 t0 = Ba[r][cb];      bh[j][0] = t0.x; bl[j][0] = t0.y;
                uint2 t1 = Ba[r][cb + 4];  bh[j][1] = t1.x; bl[j][1] = t1.y;
            }
#pragma unroll
            for (int i = 0; i < MI; i++)
#pragma unroll
                for (int j = 0; j < NI; j++) {
                    mma_bf16(acc[i][j], ah[i], bl[j]);
                    mma_bf16(acc[i][j], al[i], bh[j]);
                    mma_bf16(acc[i][j], ah[i], bh[j]);
                }
        }
        __syncthreads();
    }

#pragma unroll
    for (int i = 0; i < MI; i++)
#pragma unroll
        for (int j = 0; j < NI; j++) {
            int row = m0 + warp_m + i * 16 + (lane >> 2);
            int col = n0 + warp_n + j * 8 + 2 * (lane & 3);
#pragma unroll
            for (int q = 0; q < 4; q++) {
                int gr = row + (q >> 1) * 8;
                int gc = col + (q & 1);
                if (gc < N) {
                    float r = acc[i][j][q];
                    if (bias) r += bias[gc];
                    size_t off = (size_t)gr * N + gc;
                    if (accum) r += C[off];
                    C[off] = r;
                }
            }
        }
}

// ============ 3xBF16 energy GEMM + fused score (uint2 interleaved) ==========
// T = enc[8192,1024] @ U[1024,1024]^T; epilogue: partial score
// sum_cols v * tanh(T + Ub + hW) per row, 32 deterministic slots.
// BM=128, BN=64, BK=32; warp grid 4(M)x2(N), warp tile 32x32 (MI=2, NI=4).
__global__ void __launch_bounds__(256, 2)
tgemm_score_kernel(const float* __restrict__ enc, const float* __restrict__ U,
                   const float* __restrict__ Ub, const float* __restrict__ v)
{
    constexpr int BM = 128, BN = 64, BK = 32;
    constexpr int MI = 2;               // WM=32
    constexpr int NI = 4;               // WN=32
    constexpr int PP = BK / 2;          // 16
    constexpr int KPP = PP + 4;         // 20
    constexpr int F4R = BK / 4;         // 8
    constexpr int RPP = 256 / F4R;      // 32

    __shared__ uint2 Aa[BM][KPP];
    __shared__ uint2 Ba[BN][KPP];

    const int tid = threadIdx.x;
    const int lane = tid & 31;
    const int w = tid >> 5;
    const int lane4 = lane >> 2;
    const int lanek = lane & 3;
    const int warp_m = (w & 3) * 32;    // 4 warps along M
    const int warp_n = (w >> 2) * 32;   // 2 warps along N
    const int m0 = blockIdx.y * BM;
    const int n0 = blockIdx.x * BN;
    const int lrow = tid / F4R;
    const int lk4 = (tid % F4R) * 4;
    const int lp = lk4 >> 1;

    float acc[MI][NI][4];
#pragma unroll
    for (int i = 0; i < MI; i++)
#pragma unroll
        for (int j = 0; j < NI; j++)
#pragma unroll
            for (int q = 0; q < 4; q++) acc[i][j][q] = 0.f;

    for (int k0 = 0; k0 < Hq; k0 += BK) {
#pragma unroll
        for (int r = lrow; r < BM; r += RPP) {
            float4 vv = *reinterpret_cast<const float4*>(
                enc + (size_t)(m0 + r) * Hq + k0 + lk4);
            float hx, lx, hy, ly, hz, lz, hw, lw;
            split_bf16(vv.x, hx, lx); split_bf16(vv.y, hy, ly);
            split_bf16(vv.z, hz, lz); split_bf16(vv.w, hw, lw);
            Aa[r][lp]     = make_uint2(pack2(hx, hy), pack2(lx, ly));
            Aa[r][lp + 1] = make_uint2(pack2(hz, hw), pack2(lz, lw));
        }
#pragma unroll
        for (int r = lrow; r < BN; r += RPP) {
            float4 vv = *reinterpret_cast<const float4*>(
                U + (size_t)(n0 + r) * Hq + k0 + lk4);
            float hx, lx, hy, ly, hz, lz, hw, lw;
            split_bf16(vv.x, hx, lx); split_bf16(vv.y, hy, ly);
            split_bf16(vv.z, hz, lz); split_bf16(vv.w, hw, lw);
            Ba[r][lp]     = make_uint2(pack2(hx, hy), pack2(lx, ly));
            Ba[r][lp + 1] = make_uint2(pack2(hz, hw), pack2(lz, lw));
        }
        __syncthreads();

#pragma unroll
        for (int kk = 0; kk < PP; kk += 8) {
            unsigned ah[MI][4], al[MI][4], bh[NI][2], bl[NI][2];
#pragma unroll
            for (int i = 0; i < MI; i++) {
                int r = warp_m + i * 16 + lane4;
                int cb = kk + lanek;
                uint2 t0 = Aa[r][cb];      ah[i][0] = t0.x; al[i][0] = t0.y;
                uint2 t1 = Aa[r + 8][cb];  ah[i][1] = t1.x; al[i][1] = t1.y;
                uint2 t2 = Aa[r][cb + 4];  ah[i][2] = t2.x; al[i][2] = t2.y;
                uint2 t3 = Aa[r + 8][cb + 4]; ah[i][3] = t3.x; al[i][3] = t3.y;
            }
#pragma unroll
            for (int j = 0; j < NI; j++) {
                int r = warp_n + j * 8 + lane4;
                int cb = kk + lanek;
                uint2 t0 = Ba[r][cb];      bh[j][0] = t0.x; bl[j][0] = t0.y;
                uint2 t1 = Ba[r][cb + 4];  bh[j][1] = t1.x; bl[j][1] = t1.y;
            }
#pragma unroll
            for (int i = 0; i < MI; i++)
#pragma unroll
                for (int j = 0; j < NI; j++) {
                    mma_bf16(acc[i][j], ah[i], bl[j]);
                    mma_bf16(acc[i][j], al[i], bh[j]);
                    mma_bf16(acc[i][j], ah[i], bh[j]);
                }
        }
        __syncthreads();
    }

    // ---- fused score epilogue over this warp's 32 columns ------------------
    float vv[NI][2], uu[NI][2];
#pragma unroll
    for (int j = 0; j < NI; j++)
#pragma unroll
        for (int qc = 0; qc < 2; qc++) {
            int c = n0 + warp_n + j * 8 + 2 * lanek + qc;
            vv[j][qc] = v[c];
            uu[j][qc] = Ub[c];
        }

    const int slot = blockIdx.x * 2 + (w >> 2);   // 16 blocks x 2 n-warps = 32
#pragma unroll
    for (int i = 0; i < MI; i++)
#pragma unroll
        for (int qr = 0; qr < 2; qr++) {
            int row = m0 + warp_m + i * 16 + lane4 + qr * 8;
            int b = row & (Bq - 1);
            const float* hwr = g_hW + (size_t)b * Hq + n0 + warp_n + 2 * lanek;
            float part = 0.f;
#pragma unroll
            for (int j = 0; j < NI; j++)
#pragma unroll
                for (int qc = 0; qc < 2; qc++) {
                    float t = acc[i][j][2 * qr + qc] + uu[j][qc]
                              + hwr[j * 8 + qc];
                    part += vv[j][qc] * tanh_fast(t);
                }
            part += __shfl_xor_sync(0xffffffffu, part, 1);
            part += __shfl_xor_sync(0xffffffffu, part, 2);
            if (lanek == 0)
                g_spart[(size_t)slot * SBq + row] = part;
        }
}

// ====== logits GEMM: cp.async 4-stage pipelined, raw-tf32 (truncation) ======
// C[64, V] = h[64,1024] @ out_W[V,1024]^T + out_b. BM=64, BN=128, BK=32.
#define LG_STAGES 4
#define LG_KP 36                        /* padded row, units of 4B */
#define LG_AOFF 0                       /* A: 64 rows */
#define LG_BOFF (64 * LG_KP)            /* B: 128 rows */
#define LG_STG ((64 + 128) * LG_KP)     /* u32 per stage = 6912 */
#define LG_SMEM (LG_STAGES * LG_STG * 4)   /* 110592 B */

__global__ void __launch_bounds__(256)
logits_kernel(const float* __restrict__ A, const float* __restrict__ Bm,
              float* __restrict__ C, const float* __restrict__ bias)
{
    extern __shared__ unsigned sml[];
    constexpr int MI = 2, NI = 4;       // WM=32, WN=32; warp grid 2(M)x4(N)
    const int N = Vq, K = Hq;

    const int tid = threadIdx.x;
    const int lane = tid & 31;
    const int w = tid >> 5;
    const int warp_m = (w & 1) * 32;
    const int warp_n = (w >> 1) * 32;
    const int n0 = blockIdx.x * 128;
    const int lrow = tid >> 3;          // 0..31
    const int lk4 = (tid & 7) * 4;      // float offset in row

    const float* Abase = A + (size_t)lrow * K + lk4;
    const float* Bbase = Bm + (size_t)(n0 + lrow) * K + lk4;

    float acc[MI][NI][4];
#pragma unroll
    for (int i = 0; i < MI; i++)
#pragma unroll
        for (int j = 0; j < NI; j++)
#pragma unroll
            for (int q = 0; q < 4; q++) acc[i][j][q] = 0.f;

    auto issue = [&](int ch) {
        unsigned* st = sml + (ch & (LG_STAGES - 1)) * LG_STG;
        int k0 = ch * 32;
        uint32_t abase = smem_u32(st);
#pragma unroll
        for (int u = 0; u < 2; u++) {
            int r = lrow + u * 32;
            cp16(abase + (LG_AOFF + r * LG_KP + lk4) * 4,
                 Abase + (size_t)u * 32 * K + k0, 1);
        }
#pragma unroll
        for (int u = 0; u < 4; u++) {
            int r = lrow + u * 32;
            cp16(abase + (LG_BOFF + r * LG_KP + lk4) * 4,
                 Bbase + (size_t)u * 32 * K + k0, (n0 + r) < N);
        }
        cp_commit();
    };

    issue(0); issue(1); issue(2);

    for (int ch = 0; ch < 32; ch++) {
        cp_wait<2>();
        __syncthreads();
        const unsigned* st = sml + (ch & (LG_STAGES - 1)) * LG_STG;

#pragma unroll
        for (int kk = 0; kk < 32; kk += 8) {
            unsigned af[MI][4], bf[NI][2];
#pragma unroll
            for (int i = 0; i < MI; i++) {
                int r = warp_m + i * 16 + (lane >> 2);
                int cb = kk + (lane & 3);
                af[i][0] = st[LG_AOFF + r * LG_KP + cb];
                af[i][1] = st[LG_AOFF + (r + 8) * LG_KP + cb];
                af[i][2] = st[LG_AOFF + r * LG_KP + cb + 4];
                af[i][3] = st[LG_AOFF + (r + 8) * LG_KP + cb + 4];
            }
#pragma unroll
            for (int j = 0; j < NI; j++) {
                int r = warp_n + j * 8 + (lane >> 2);
                int cb = kk + (lane & 3);
                bf[j][0] = st[LG_BOFF + r * LG_KP + cb];
                bf[j][1] = st[LG_BOFF + r * LG_KP + cb + 4];
            }
#pragma unroll
            for (int i = 0; i < MI; i++)
#pragma unroll
                for (int j = 0; j < NI; j++)
                    mma_tf32(acc[i][j], af[i], bf[j]);
        }

        if (ch + 3 < 32) issue(ch + 3);
        else cp_commit();               // keep group count consistent
    }

#pragma unroll
    for (int i = 0; i < MI; i++)
#pragma unroll
        for (int j = 0; j < NI; j++) {
            int row = warp_m + i * 16 + (lane >> 2);
            int col = n0 + warp_n + j * 8 + 2 * (lane & 3);
#pragma unroll
            for (int q = 0; q < 4; q++) {
                int gr = row + (q >> 1) * 8;
                int gc = col + (q & 1);
                if (gc < N)
                    C[(size_t)gr * N + gc] = acc[i][j][q] + bias[gc];
            }
        }
}

// ---------------- pointwise / reduction kernels -----------------------------
__global__ void softmax_kernel(float* __restrict__ attn_out)
{
    __shared__ float sm[Sq];
    int b = blockIdx.x, t = threadIdx.x;
    float x = 0.f;
#pragma unroll
    for (int q = 0; q < NSLOT; q++)
        x += g_spart[(size_t)q * SBq + t * Bq + b];
    sm[t] = x; __syncthreads();
    for (int o = 64; o > 0; o >>= 1) {
        if (t < o) sm[t] = fmaxf(sm[t], sm[t + o]);
        __syncthreads();
    }
    float m = sm[0];
    __syncthreads();
    float e = expf(x - m);
    sm[t] = e; __syncthreads();
    for (int o = 64; o > 0; o >>= 1) {
        if (t < o) sm[t] += sm[t + o];
        __syncthreads();
    }
    attn_out[b * Sq + t] = e / sm[0];
}

__global__ void context_kernel(const float* __restrict__ attn,
                               const float* __restrict__ enc)
{
    __shared__ float aw[Sq];
    int idx = blockIdx.x * 256 + threadIdx.x;
    int b = idx >> 10;
    int h = idx & (Hq - 1);
    if (threadIdx.x < Sq) aw[threadIdx.x] = attn[b * Sq + threadIdx.x];
    __syncthreads();
    float acc = 0.f;
#pragma unroll 4
    for (int s = 0; s < Sq; s++)
        acc = fmaf(aw[s], enc[((size_t)s * Bq + b) * Hq + h], acc);
    g_ctx[idx] = acc;
}

__global__ void xbuild_kernel(const int* __restrict__ seq,
                              const float* __restrict__ emb)
{
    int idx = blockIdx.x * 256 + threadIdx.x;
    int b = idx / KIq;
    int j = idx - b * KIq;
    float val;
    if (j < Eq) val = emb[(size_t)seq[b] * Eq + j];
    else        val = g_ctx[b * Hq + (j - Eq)];
    g_x[idx] = val;
}

__device__ __forceinline__ float sigf(float x) { return 1.f / (1.f + expf(-x)); }

__global__ void lstm_kernel(const float* __restrict__ c0,
                            float* __restrict__ h_new,
                            float* __restrict__ c_new)
{
    int idx = blockIdx.x * 256 + threadIdx.x;
    int b = idx >> 10;
    int h = idx & (Hq - 1);
    const float* g = g_gates + ((size_t)b << 12);
    float vi = g[h];
    float vf = g[Hq + h];
    float vg = g[2 * Hq + h];
    float vo = g[3 * Hq + h];
    float c = sigf(vf) * c0[idx] + sigf(vi) * tanhf(vg);
    c_new[idx] = c;
    h_new[idx] = sigf(vo) * tanhf(c);
}

__device__ __forceinline__ float blk_red_max(float v, float* red)
{
    int t = threadIdx.x;
#pragma unroll
    for (int o = 16; o > 0; o >>= 1) v = fmaxf(v, __shfl_xor_sync(~0u, v, o));
    if ((t & 31) == 0) red[t >> 5] = v;
    __syncthreads();
    if (t < 32) {
        v = red[t];
#pragma unroll
        for (int o = 16; o > 0; o >>= 1) v = fmaxf(v, __shfl_xor_sync(~0u, v, o));
        if (t == 0) red[0] = v;
    }
    __syncthreads();
    float r = red[0];
    __syncthreads();
    return r;
}

__device__ __forceinline__ float blk_red_sum(float v, float* red)
{
    int t = threadIdx.x;
#pragma unroll
    for (int o = 16; o > 0; o >>= 1) v += __shfl_xor_sync(~0u, v, o);
    if ((t & 31) == 0) red[t >> 5] = v;
    __syncthreads();
    if (t < 32) {
        v = red[t];
#pragma unroll
        for (int o = 16; o > 0; o >>= 1) v += __shfl_xor_sync(~0u, v, o);
        if (t == 0) red[0] = v;
    }
    __syncthreads();
    float r = red[0];
    __syncthreads();
    return r;
}

__global__ void logsoftmax_kernel(float* __restrict__ out)
{
    __shared__ float red[32];
    int b = blockIdx.x;
    float* row = out + (size_t)b * Vq;
    int t = threadIdx.x;

    float m = -1e30f;
    for (int j = t; j < Vq; j += 1024) m = fmaxf(m, row[j]);
    m = blk_red_max(m, red);

    float s = 0.f;
    for (int j = t; j < Vq; j += 1024) s += expf(row[j] - m);
    s = blk_red_sum(s, red);

    float lse = m + logf(s);
    for (int j = t; j < Vq; j += 1024) row[j] -= lse;
}

// ---------------------------------------------------------------------------
extern "C" void kernel_launch(void* const* d_in, const int* in_sizes, int n_in,
                              void* d_out, int out_size)
{
    const int*   seq     = (const int*)d_in[0];
    const float* h0      = (const float*)d_in[1];
    const float* c0      = (const float*)d_in[2];
    const float* enc     = (const float*)d_in[3];
    const float* emb     = (const float*)d_in[4];
    const float* W_ih    = (const float*)d_in[5];
    const float* W_hh    = (const float*)d_in[6];
    const float* b_ih    = (const float*)d_in[7];
    const float* b_hh    = (const float*)d_in[8];
    const float* attn_W  = (const float*)d_in[9];
    const float* attn_Wb = (const float*)d_in[10];
    const float* attn_U  = (const float*)d_in[11];
    const float* attn_Ub = (const float*)d_in[12];
    const float* attn_v  = (const float*)d_in[13];
    const float* out_W   = (const float*)d_in[14];
    const float* out_b   = (const float*)d_in[15];

    float* out      = (float*)d_out;
    float* o_logits = out;                          // [B, V]
    float* o_h      = out + (size_t)Bq * Vq;        // [1, B, H]
    float* o_c      = o_h + Bq * Hq;                // [1, B, H]
    float* o_attn   = o_c + Bq * Hq;                // [B, 1, S]

    float *hW, *x, *gates;
    cudaGetSymbolAddress((void**)&hW,    g_hW);
    cudaGetSymbolAddress((void**)&x,     g_x);
    cudaGetSymbolAddress((void**)&gates, g_gates);

    cudaFuncSetAttribute(logits_kernel,
                         cudaFuncAttributeMaxDynamicSharedMemorySize, LG_SMEM);

    // 1) hW = h0 @ attn_W^T + attn_Wb            [64, 1024]   (3xBF16)
    mma3bf_gemm_nt<64, 128, 32, 32, 32><<<dim3(Hq / 128, 1), 256>>>(
        h0, attn_W, hW, Bq, Hq, Hq, attn_Wb, 0);

    // 2) fused energy GEMM (3xBF16, uint2 interleaved) + score partials
    tgemm_score_kernel<<<dim3(Hq / 64, SBq / 128), 256>>>(
        enc, attn_U, attn_Ub, attn_v);

    // 3) attn = softmax(reduce(spart)) -> output region
    softmax_kernel<<<Bq, Sq>>>(o_attn);

    // 4) context = attn @ enc                    [64, 1024]
    context_kernel<<<Bq * Hq / 256, 256>>>(o_attn, enc);

    // 5) x = [emb[seq] ; context]                [64, 1536]
    xbuild_kernel<<<Bq * KIq / 256, 256>>>(seq, emb);

    // 6) gates  = x @ W_ih^T + b_ih              [64, 4096]   (3xBF16)
    mma3bf_gemm_nt<64, 128, 32, 32, 32><<<dim3(G4q / 128, 1), 256>>>(
        x, W_ih, gates, Bq, G4q, KIq, b_ih, 0);

    // 7) gates += h0 @ W_hh^T + b_hh                          (3xBF16)
    mma3bf_gemm_nt<64, 128, 32, 32, 32><<<dim3(G4q / 128, 1), 256>>>(
        h0, W_hh, gates, Bq, G4q, Hq, b_hh, 1);

    // 8) LSTM pointwise -> h_new, c_new in output
    lstm_kernel<<<Bq * Hq / 256, 256>>>(c0, o_h, o_c);

    // 9) logits = h_new @ out_W^T + out_b  [64, 50257]  (cp.async tf32)
    logits_kernel<<<dim3((Vq + 127) / 128, 1), 256, LG_SMEM>>>(
        o_h, out_W, o_logits, out_b);

    // 10) in-place log_softmax over V
    logsoftmax_kernel<<<Bq, 1024>>>(o_logits);
}

// round 12
// speedup vs baseline: 1.4182x; 1.0397x over previous
#include <cuda_runtime.h>
#include <cuda_bf16.h>
#include <math.h>
#include <stdint.h>

#define Bq 64
#define Sq 128
#define Eq 512
#define Hq 1024
#define Vq 50257
#define K2q 2560        /* E + H + H : fused gates K */
#define G4q (4 * Hq)    /* 4096 */
#define SBq (Sq * Bq)   /* 8192 */
#define NSLOT 32
#define LSC 6304        /* log-softmax chunk: 8*6304 >= V */

// ---------------- scratch (static device globals; no runtime allocation) ----
__device__ float g_hW[Bq * Hq];
__device__ float g_spart[NSLOT * SBq];
__device__ float g_ctx[Bq * Hq];
__device__ float g_x2[Bq * K2q];       // [emb ; ctx ; h]
__device__ float g_gates[Bq * G4q];
__device__ float g_lsm[Bq * 8];
__device__ float g_lss[Bq * 8];

// ---------------- helpers ---------------------------------------------------
__device__ __forceinline__ void split_bf16(float x, float& hi, float& lo)
{
    hi = __bfloat162float(__float2bfloat16(x));
    lo = x - hi;
}

__device__ __forceinline__ unsigned pack2(float e0, float e1)
{
    unsigned r;
    asm("cvt.rn.bf16x2.f32 %0, %1, %2;" : "=r"(r) : "f"(e1), "f"(e0));
    return r;
}

__device__ __forceinline__ void mma_bf16(float c[4], const unsigned a[4],
                                         const unsigned b[2])
{
    asm volatile(
        "mma.sync.aligned.m16n8k16.row.col.f32.bf16.bf16.f32 "
        "{%0,%1,%2,%3}, {%4,%5,%6,%7}, {%8,%9}, {%0,%1,%2,%3};"
        : "+f"(c[0]), "+f"(c[1]), "+f"(c[2]), "+f"(c[3])
        : "r"(a[0]), "r"(a[1]), "r"(a[2]), "r"(a[3]), "r"(b[0]), "r"(b[1]));
}

__device__ __forceinline__ float tanh_fast(float x)
{
    float cx = fminf(fmaxf(x, -15.f), 15.f);
    float e = __expf(2.f * cx);
    return __fdividef(e - 1.f, e + 1.f);
}

// ================== 3xBF16 GEMM template (hi/lo interleaved uint2) ==========
// C[M,N] = A[M,K] @ B[N,K]^T (+bias). M%BM==0, K%BK==0, N ragged.
template <int BM, int BN, int BK, int WM, int WN>
__global__ void __launch_bounds__(256)
mma3bf_gemm_nt(const float* __restrict__ A, const float* __restrict__ Bm,
               float* __restrict__ C, int M, int N, int K,
               const float* __restrict__ bias)
{
    constexpr int MI = WM / 16;
    constexpr int NI = WN / 8;
    constexpr int PP = BK / 2;
    constexpr int KPP = PP + 4;
    constexpr int F4R = BK / 4;
    constexpr int RPP = 256 / F4R;

    __shared__ uint2 Aa[BM][KPP];
    __shared__ uint2 Ba[BN][KPP];

    const int tid = threadIdx.x;
    const int lane = tid & 31;
    const int w = tid >> 5;
    const int warp_m = (w % (BM / WM)) * WM;
    const int warp_n = (w / (BM / WM)) * WN;
    const int m0 = blockIdx.y * BM;
    const int n0 = blockIdx.x * BN;
    const int lrow = tid / F4R;
    const int lk4 = (tid % F4R) * 4;
    const int lp = lk4 >> 1;

    float acc[MI][NI][4];
#pragma unroll
    for (int i = 0; i < MI; i++)
#pragma unroll
        for (int j = 0; j < NI; j++)
#pragma unroll
            for (int q = 0; q < 4; q++) acc[i][j][q] = 0.f;

    for (int k0 = 0; k0 < K; k0 += BK) {
#pragma unroll
        for (int r = lrow; r < BM; r += RPP) {
            float4 vv = *reinterpret_cast<const float4*>(
                A + (size_t)(m0 + r) * K + k0 + lk4);
            float hx, lx, hy, ly, hz, lz, hw, lw;
            split_bf16(vv.x, hx, lx); split_bf16(vv.y, hy, ly);
            split_bf16(vv.z, hz, lz); split_bf16(vv.w, hw, lw);
            Aa[r][lp]     = make_uint2(pack2(hx, hy), pack2(lx, ly));
            Aa[r][lp + 1] = make_uint2(pack2(hz, hw), pack2(lz, lw));
        }
#pragma unroll
        for (int r = lrow; r < BN; r += RPP) {
            float4 vv = make_float4(0.f, 0.f, 0.f, 0.f);
            if (n0 + r < N)
                vv = *reinterpret_cast<const float4*>(
                    Bm + (size_t)(n0 + r) * K + k0 + lk4);
            float hx, lx, hy, ly, hz, lz, hw, lw;
            split_bf16(vv.x, hx, lx); split_bf16(vv.y, hy, ly);
            split_bf16(vv.z, hz, lz); split_bf16(vv.w, hw, lw);
            Ba[r][lp]     = make_uint2(pack2(hx, hy), pack2(lx, ly));
            Ba[r][lp + 1] = make_uint2(pack2(hz, hw), pack2(lz, lw));
        }
        __syncthreads();

#pragma unroll
        for (int kk = 0; kk < PP; kk += 8) {
            unsigned ah[MI][4], al[MI][4], bh[NI][2], bl[NI][2];
#pragma unroll
            for (int i = 0; i < MI; i++) {
                int r = warp_m + i * 16 + (lane >> 2);
                int cb = kk + (lane & 3);
                uint2 t0 = Aa[r][cb];      ah[i][0] = t0.x; al[i][0] = t0.y;
                uint2 t1 = Aa[r + 8][cb];  ah[i][1] = t1.x; al[i][1] = t1.y;
                uint2 t2 = Aa[r][cb + 4];  ah[i][2] = t2.x; al[i][2] = t2.y;
                uint2 t3 = Aa[r + 8][cb + 4]; ah[i][3] = t3.x; al[i][3] = t3.y;
            }
#pragma unroll
            for (int j = 0; j < NI; j++) {
                int r = warp_n + j * 8 + (lane >> 2);
                int cb = kk + (lane & 3);
                uint2 t0 = Ba[r][cb];      bh[j][0] = t0.x; bl[j][0] = t0.y;
                uint2 t1 = Ba[r][cb + 4];  bh[j][1] = t1.x; bl[j][1] = t1.y;
            }
#pragma unroll
            for (int i = 0; i < MI; i++)
#pragma unroll
                for (int j = 0; j < NI; j++) {
                    mma_bf16(acc[i][j], ah[i], bl[j]);
                    mma_bf16(acc[i][j], al[i], bh[j]);
                    mma_bf16(acc[i][j], ah[i], bh[j]);
                }
        }
        __syncthreads();
    }

#pragma unroll
    for (int i = 0; i < MI; i++)
#pragma unroll
        for (int j = 0; j < NI; j++) {
            int row = m0 + warp_m + i * 16 + (lane >> 2);
            int col = n0 + warp_n + j * 8 + 2 * (lane & 3);
#pragma unroll
            for (int q = 0; q < 4; q++) {
                int gr = row + (q >> 1) * 8;
                int gc = col + (q & 1);
                if (gc < N) {
                    float r = acc[i][j][q];
                    if (bias) r += bias[gc];
                    C[(size_t)gr * N + gc] = r;
                }
            }
        }
}

// ============ fused gates GEMM: [x2] @ [W_ih;W_hh]^T, K=2560, 3xBF16 ========
// gates[64,4096] = x2[64,2560] @ Wcat^T + b_ih + b_hh. BM=64, BN=64, WM=32,
// WN=16 (MI=2, NI=2), 64 blocks.
__global__ void __launch_bounds__(256)
gates_kernel(const float* __restrict__ W1, const float* __restrict__ W2,
             const float* __restrict__ b1, const float* __restrict__ b2)
{
    constexpr int BM = 64, BN = 64, BK = 32;
    constexpr int MI = 2, NI = 2;
    constexpr int PP = 16, KPP = 20;

    __shared__ uint2 Aa[BM][KPP];
    __shared__ uint2 Ba[BN][KPP];

    const int tid = threadIdx.x;
    const int lane = tid & 31;
    const int w = tid >> 5;
    const int warp_m = (w % 2) * 32;
    const int warp_n = (w / 2) * 16;
    const int n0 = blockIdx.x * BN;
    const int lrow = tid >> 3;          // 0..31
    const int lk4 = (tid & 7) * 4;
    const int lp = lk4 >> 1;

    float acc[MI][NI][4];
#pragma unroll
    for (int i = 0; i < MI; i++)
#pragma unroll
        for (int j = 0; j < NI; j++)
#pragma unroll
            for (int q = 0; q < 4; q++) acc[i][j][q] = 0.f;

    for (int k0 = 0; k0 < K2q; k0 += BK) {
#pragma unroll
        for (int r = lrow; r < BM; r += 32) {
            float4 vv = *reinterpret_cast<const float4*>(
                g_x2 + (size_t)r * K2q + k0 + lk4);
            float hx, lx, hy, ly, hz, lz, hw, lw;
            split_bf16(vv.x, hx, lx); split_bf16(vv.y, hy, ly);
            split_bf16(vv.z, hz, lz); split_bf16(vv.w, hw, lw);
            Aa[r][lp]     = make_uint2(pack2(hx, hy), pack2(lx, ly));
            Aa[r][lp + 1] = make_uint2(pack2(hz, hw), pack2(lz, lw));
        }
#pragma unroll
        for (int r = lrow; r < BN; r += 32) {
            const float* src = (k0 < 1536)
                ? W1 + (size_t)(n0 + r) * 1536 + k0 + lk4
                : W2 + (size_t)(n0 + r) * Hq + (k0 - 1536) + lk4;
            float4 vv = *reinterpret_cast<const float4*>(src);
            float hx, lx, hy, ly, hz, lz, hw, lw;
            split_bf16(vv.x, hx, lx); split_bf16(vv.y, hy, ly);
            split_bf16(vv.z, hz, lz); split_bf16(vv.w, hw, lw);
            Ba[r][lp]     = make_uint2(pack2(hx, hy), pack2(lx, ly));
            Ba[r][lp + 1] = make_uint2(pack2(hz, hw), pack2(lz, lw));
        }
        __syncthreads();

#pragma unroll
        for (int kk = 0; kk < PP; kk += 8) {
            unsigned ah[MI][4], al[MI][4], bh[NI][2], bl[NI][2];
#pragma unroll
            for (int i = 0; i < MI; i++) {
                int r = warp_m + i * 16 + (lane >> 2);
                int cb = kk + (lane & 3);
                uint2 t0 = Aa[r][cb];      ah[i][0] = t0.x; al[i][0] = t0.y;
                uint2 t1 = Aa[r + 8][cb];  ah[i][1] = t1.x; al[i][1] = t1.y;
                uint2 t2 = Aa[r][cb + 4];  ah[i][2] = t2.x; al[i][2] = t2.y;
                uint2 t3 = Aa[r + 8][cb + 4]; ah[i][3] = t3.x; al[i][3] = t3.y;
            }
#pragma unroll
            for (int j = 0; j < NI; j++) {
                int r = warp_n + j * 8 + (lane >> 2);
                int cb = kk + (lane & 3);
                uint2 t0 = Ba[r][cb];      bh[j][0] = t0.x; bl[j][0] = t0.y;
                uint2 t1 = Ba[r][cb + 4];  bh[j][1] = t1.x; bl[j][1] = t1.y;
            }
#pragma unroll
            for (int i = 0; i < MI; i++)
#pragma unroll
                for (int j = 0; j < NI; j++) {
                    mma_bf16(acc[i][j], ah[i], bl[j]);
                    mma_bf16(acc[i][j], al[i], bh[j]);
                    mma_bf16(acc[i][j], ah[i], bh[j]);
                }
        }
        __syncthreads();
    }

#pragma unroll
    for (int i = 0; i < MI; i++)
#pragma unroll
        for (int j = 0; j < NI; j++) {
            int row = warp_m + i * 16 + (lane >> 2);
            int col = n0 + warp_n + j * 8 + 2 * (lane & 3);
#pragma unroll
            for (int q = 0; q < 4; q++) {
                int gr = row + (q >> 1) * 8;
                int gc = col + (q & 1);
                g_gates[(size_t)gr * G4q + gc] =
                    acc[i][j][q] + b1[gc] + b2[gc];
            }
        }
}

// ============ 3xBF16 energy GEMM + fused score (unchanged R11) ==============
__global__ void __launch_bounds__(256, 2)
tgemm_score_kernel(const float* __restrict__ enc, const float* __restrict__ U,
                   const float* __restrict__ Ub, const float* __restrict__ v)
{
    constexpr int BM = 128, BN = 64, BK = 32;
    constexpr int MI = 2, NI = 4;
    constexpr int PP = 16, KPP = 20;
    constexpr int F4R = 8, RPP = 32;

    __shared__ uint2 Aa[BM][KPP];
    __shared__ uint2 Ba[BN][KPP];

    const int tid = threadIdx.x;
    const int lane = tid & 31;
    const int w = tid >> 5;
    const int lane4 = lane >> 2;
    const int lanek = lane & 3;
    const int warp_m = (w & 3) * 32;
    const int warp_n = (w >> 2) * 32;
    const int m0 = blockIdx.y * BM;
    const int n0 = blockIdx.x * BN;
    const int lrow = tid / F4R;
    const int lk4 = (tid % F4R) * 4;
    const int lp = lk4 >> 1;

    float acc[MI][NI][4];
#pragma unroll
    for (int i = 0; i < MI; i++)
#pragma unroll
        for (int j = 0; j < NI; j++)
#pragma unroll
            for (int q = 0; q < 4; q++) acc[i][j][q] = 0.f;

    for (int k0 = 0; k0 < Hq; k0 += BK) {
#pragma unroll
        for (int r = lrow; r < BM; r += RPP) {
            float4 vv = *reinterpret_cast<const float4*>(
                enc + (size_t)(m0 + r) * Hq + k0 + lk4);
            float hx, lx, hy, ly, hz, lz, hw, lw;
            split_bf16(vv.x, hx, lx); split_bf16(vv.y, hy, ly);
            split_bf16(vv.z, hz, lz); split_bf16(vv.w, hw, lw);
            Aa[r][lp]     = make_uint2(pack2(hx, hy), pack2(lx, ly));
            Aa[r][lp + 1] = make_uint2(pack2(hz, hw), pack2(lz, lw));
        }
#pragma unroll
        for (int r = lrow; r < BN; r += RPP) {
            float4 vv = *reinterpret_cast<const float4*>(
                U + (size_t)(n0 + r) * Hq + k0 + lk4);
            float hx, lx, hy, ly, hz, lz, hw, lw;
            split_bf16(vv.x, hx, lx); split_bf16(vv.y, hy, ly);
            split_bf16(vv.z, hz, lz); split_bf16(vv.w, hw, lw);
            Ba[r][lp]     = make_uint2(pack2(hx, hy), pack2(lx, ly));
            Ba[r][lp + 1] = make_uint2(pack2(hz, hw), pack2(lz, lw));
        }
        __syncthreads();

#pragma unroll
        for (int kk = 0; kk < PP; kk += 8) {
            unsigned ah[MI][4], al[MI][4], bh[NI][2], bl[NI][2];
#pragma unroll
            for (int i = 0; i < MI; i++) {
                int r = warp_m + i * 16 + lane4;
                int cb = kk + lanek;
                uint2 t0 = Aa[r][cb];      ah[i][0] = t0.x; al[i][0] = t0.y;
                uint2 t1 = Aa[r + 8][cb];  ah[i][1] = t1.x; al[i][1] = t1.y;
                uint2 t2 = Aa[r][cb + 4];  ah[i][2] = t2.x; al[i][2] = t2.y;
                uint2 t3 = Aa[r + 8][cb + 4]; ah[i][3] = t3.x; al[i][3] = t3.y;
            }
#pragma unroll
            for (int j = 0; j < NI; j++) {
                int r = warp_n + j * 8 + lane4;
                int cb = kk + lanek;
                uint2 t0 = Ba[r][cb];      bh[j][0] = t0.x; bl[j][0] = t0.y;
                uint2 t1 = Ba[r][cb + 4];  bh[j][1] = t1.x; bl[j][1] = t1.y;
            }
#pragma unroll
            for (int i = 0; i < MI; i++)
#pragma unroll
                for (int j = 0; j < NI; j++) {
                    mma_bf16(acc[i][j], ah[i], bl[j]);
                    mma_bf16(acc[i][j], al[i], bh[j]);
                    mma_bf16(acc[i][j], ah[i], bh[j]);
                }
        }
        __syncthreads();
    }

    float vv[NI][2], uu[NI][2];
#pragma unroll
    for (int j = 0; j < NI; j++)
#pragma unroll
        for (int qc = 0; qc < 2; qc++) {
            int c = n0 + warp_n + j * 8 + 2 * lanek + qc;
            vv[j][qc] = v[c];
            uu[j][qc] = Ub[c];
        }

    const int slot = blockIdx.x * 2 + (w >> 2);
#pragma unroll
    for (int i = 0; i < MI; i++)
#pragma unroll
        for (int qr = 0; qr < 2; qr++) {
            int row = m0 + warp_m + i * 16 + lane4 + qr * 8;
            int b = row & (Bq - 1);
            const float* hwr = g_hW + (size_t)b * Hq + n0 + warp_n + 2 * lanek;
            float part = 0.f;
#pragma unroll
            for (int j = 0; j < NI; j++)
#pragma unroll
                for (int qc = 0; qc < 2; qc++) {
                    float t = acc[i][j][2 * qr + qc] + uu[j][qc]
                              + hwr[j * 8 + qc];
                    part += vv[j][qc] * tanh_fast(t);
                }
            part += __shfl_xor_sync(0xffffffffu, part, 1);
            part += __shfl_xor_sync(0xffffffffu, part, 2);
            if (lanek == 0)
                g_spart[(size_t)slot * SBq + row] = part;
        }
}

// ====== logits GEMM: single-pass bf16 m16n8k16 ==============================
// C[64, V] = h[64,1024] @ out_W[V,1024]^T + out_b. BM=64, BN=128, BK=32.
__global__ void __launch_bounds__(256)
logits_kernel(const float* __restrict__ A, const float* __restrict__ Bm,
              float* __restrict__ C, const float* __restrict__ bias)
{
    constexpr int BM = 64, BN = 128, BK = 32;
    constexpr int MI = 2, NI = 4;       // WM=32, WN=32; warp grid 2(M)x4(N)
    constexpr int PP = 16, KPP = 20;
    const int N = Vq, K = Hq;

    __shared__ unsigned Aa[BM][KPP];
    __shared__ unsigned Ba[BN][KPP];

    const int tid = threadIdx.x;
    const int lane = tid & 31;
    const int w = tid >> 5;
    const int warp_m = (w & 1) * 32;
    const int warp_n = (w >> 1) * 32;
    const int n0 = blockIdx.x * BN;
    const int lrow = tid >> 3;          // 0..31
    const int lk4 = (tid & 7) * 4;
    const int lp = lk4 >> 1;

    float acc[MI][NI][4];
#pragma unroll
    for (int i = 0; i < MI; i++)
#pragma unroll
        for (int j = 0; j < NI; j++)
#pragma unroll
            for (int q = 0; q < 4; q++) acc[i][j][q] = 0.f;

    for (int k0 = 0; k0 < K; k0 += BK) {
#pragma unroll
        for (int r = lrow; r < BM; r += 32) {
            float4 vv = *reinterpret_cast<const float4*>(
                A + (size_t)r * K + k0 + lk4);
            Aa[r][lp]     = pack2(vv.x, vv.y);
            Aa[r][lp + 1] = pack2(vv.z, vv.w);
        }
#pragma unroll
        for (int r = lrow; r < BN; r += 32) {
            float4 vv = make_float4(0.f, 0.f, 0.f, 0.f);
            if (n0 + r < N)
                vv = *reinterpret_cast<const float4*>(
                    Bm + (size_t)(n0 + r) * K + k0 + lk4);
            Ba[r][lp]     = pack2(vv.x, vv.y);
            Ba[r][lp + 1] = pack2(vv.z, vv.w);
        }
        __syncthreads();

#pragma unroll
        for (int kk = 0; kk < PP; kk += 8) {
            unsigned af[MI][4], bf[NI][2];
#pragma unroll
            for (int i = 0; i < MI; i++) {
                int r = warp_m + i * 16 + (lane >> 2);
                int cb = kk + (lane & 3);
                af[i][0] = Aa[r][cb];     af[i][1] = Aa[r + 8][cb];
                af[i][2] = Aa[r][cb + 4]; af[i][3] = Aa[r + 8][cb + 4];
            }
#pragma unroll
            for (int j = 0; j < NI; j++) {
                int r = warp_n + j * 8 + (lane >> 2);
                int cb = kk + (lane & 3);
                bf[j][0] = Ba[r][cb]; bf[j][1] = Ba[r][cb + 4];
            }
#pragma unroll
            for (int i = 0; i < MI; i++)
#pragma unroll
                for (int j = 0; j < NI; j++)
                    mma_bf16(acc[i][j], af[i], bf[j]);
        }
        __syncthreads();
    }

#pragma unroll
    for (int i = 0; i < MI; i++)
#pragma unroll
        for (int j = 0; j < NI; j++) {
            int row = warp_m + i * 16 + (lane >> 2);
            int col = n0 + warp_n + j * 8 + 2 * (lane & 3);
#pragma unroll
            for (int q = 0; q < 4; q++) {
                int gr = row + (q >> 1) * 8;
                int gc = col + (q & 1);
                if (gc < N)
                    C[(size_t)gr * N + gc] = acc[i][j][q] + bias[gc];
            }
        }
}

// ---------------- pointwise / reduction kernels -----------------------------
__global__ void softmax_kernel(float* __restrict__ attn_out)
{
    __shared__ float sm[Sq];
    int b = blockIdx.x, t = threadIdx.x;
    float x = 0.f;
#pragma unroll
    for (int q = 0; q < NSLOT; q++)
        x += g_spart[(size_t)q * SBq + t * Bq + b];
    sm[t] = x; __syncthreads();
    for (int o = 64; o > 0; o >>= 1) {
        if (t < o) sm[t] = fmaxf(sm[t], sm[t + o]);
        __syncthreads();
    }
    float m = sm[0];
    __syncthreads();
    float e = expf(x - m);
    sm[t] = e; __syncthreads();
    for (int o = 64; o > 0; o >>= 1) {
        if (t < o) sm[t] += sm[t + o];
        __syncthreads();
    }
    attn_out[b * Sq + t] = e / sm[0];
}

__global__ void context_kernel(const float* __restrict__ attn,
                               const float* __restrict__ enc)
{
    __shared__ float aw[Sq];
    int idx = blockIdx.x * 256 + threadIdx.x;
    int b = idx >> 10;
    int h = idx & (Hq - 1);
    if (threadIdx.x < Sq) aw[threadIdx.x] = attn[b * Sq + threadIdx.x];
    __syncthreads();
    float acc = 0.f;
#pragma unroll 8
    for (int s = 0; s < Sq; s++)
        acc = fmaf(aw[s], enc[((size_t)s * Bq + b) * Hq + h], acc);
    g_ctx[idx] = acc;
}

// x2[b] = [ emb[seq[b]] (512) ; ctx[b] (1024) ; h0[b] (1024) ]
__global__ void xbuild_kernel(const int* __restrict__ seq,
                              const float* __restrict__ emb,
                              const float* __restrict__ h0)
{
    int idx = blockIdx.x * 256 + threadIdx.x;   // [0, B*K2)
    int b = idx / K2q;
    int j = idx - b * K2q;
    float val;
    if (j < Eq)            val = emb[(size_t)seq[b] * Eq + j];
    else if (j < Eq + Hq)  val = g_ctx[b * Hq + (j - Eq)];
    else                   val = h0[b * Hq + (j - Eq - Hq)];
    g_x2[idx] = val;
}

__device__ __forceinline__ float sigf(float x) { return 1.f / (1.f + expf(-x)); }

__global__ void lstm_kernel(const float* __restrict__ c0,
                            float* __restrict__ h_new,
                            float* __restrict__ c_new)
{
    int idx = blockIdx.x * 256 + threadIdx.x;
    int b = idx >> 10;
    int h = idx & (Hq - 1);
    const float* g = g_gates + ((size_t)b << 12);
    float vi = g[h];
    float vf = g[Hq + h];
    float vg = g[2 * Hq + h];
    float vo = g[3 * Hq + h];
    float c = sigf(vf) * c0[idx] + sigf(vi) * tanhf(vg);
    c_new[idx] = c;
    h_new[idx] = sigf(vo) * tanhf(c);
}

// ---- two-phase log-softmax (512-block parallel) ----------------------------
__global__ void ls_partial_kernel(const float* __restrict__ out)
{
    __shared__ float red[8];
    int b = blockIdx.x, c = blockIdx.y, t = threadIdx.x;
    const float* row = out + (size_t)b * Vq;
    int j0 = c * LSC;
    int j1 = min(j0 + LSC, Vq);

    float m = -1e30f;
    for (int j = j0 + t; j < j1; j += 256) m = fmaxf(m, row[j]);
#pragma unroll
    for (int o = 16; o > 0; o >>= 1) m = fmaxf(m, __shfl_xor_sync(~0u, m, o));
    if ((t & 31) == 0) red[t >> 5] = m;
    __syncthreads();
    if (t < 32) {
        float v = (t < 8) ? red[t] : -1e30f;
#pragma unroll
        for (int o = 4; o > 0; o >>= 1) v = fmaxf(v, __shfl_xor_sync(~0u, v, o));
        if (t == 0) red[0] = v;
    }
    __syncthreads();
    m = red[0];
    __syncthreads();

    float s = 0.f;
    for (int j = j0 + t; j < j1; j += 256) s += expf(row[j] - m);
#pragma unroll
    for (int o = 16; o > 0; o >>= 1) s += __shfl_xor_sync(~0u, s, o);
    if ((t & 31) == 0) red[t >> 5] = s;
    __syncthreads();
    if (t < 32) {
        float v = (t < 8) ? red[t] : 0.f;
#pragma unroll
        for (int o = 4; o > 0; o >>= 1) v += __shfl_xor_sync(~0u, v, o);
        if (t == 0) {
            g_lsm[b * 8 + c] = m;
            g_lss[b * 8 + c] = v;
        }
    }
}

__global__ void ls_apply_kernel(float* __restrict__ out)
{
    int b = blockIdx.x, c = blockIdx.y, t = threadIdx.x;
    float M = -1e30f;
#pragma unroll
    for (int q = 0; q < 8; q++) M = fmaxf(M, g_lsm[b * 8 + q]);
    float S = 0.f;
#pragma unroll
    for (int q = 0; q < 8; q++)
        S += g_lss[b * 8 + q] * expf(g_lsm[b * 8 + q] - M);
    float lse = M + logf(S);

    float* row = out + (size_t)b * Vq;
    int j0 = c * LSC;
    int j1 = min(j0 + LSC, Vq);
    for (int j = j0 + t; j < j1; j += 256) row[j] -= lse;
}

// ---------------------------------------------------------------------------
extern "C" void kernel_launch(void* const* d_in, const int* in_sizes, int n_in,
                              void* d_out, int out_size)
{
    const int*   seq     = (const int*)d_in[0];
    const float* h0      = (const float*)d_in[1];
    const float* c0      = (const float*)d_in[2];
    const float* enc     = (const float*)d_in[3];
    const float* emb     = (const float*)d_in[4];
    const float* W_ih    = (const float*)d_in[5];
    const float* W_hh    = (const float*)d_in[6];
    const float* b_ih    = (const float*)d_in[7];
    const float* b_hh    = (const float*)d_in[8];
    const float* attn_W  = (const float*)d_in[9];
    const float* attn_Wb = (const float*)d_in[10];
    const float* attn_U  = (const float*)d_in[11];
    const float* attn_Ub = (const float*)d_in[12];
    const float* attn_v  = (const float*)d_in[13];
    const float* out_W   = (const float*)d_in[14];
    const float* out_b   = (const float*)d_in[15];

    float* out      = (float*)d_out;
    float* o_logits = out;                          // [B, V]
    float* o_h      = out + (size_t)Bq * Vq;        // [1, B, H]
    float* o_c      = o_h + Bq * Hq;                // [1, B, H]
    float* o_attn   = o_c + Bq * Hq;                // [B, 1, S]

    float* hW;
    cudaGetSymbolAddress((void**)&hW, g_hW);

    // 1) hW = h0 @ attn_W^T + attn_Wb            [64, 1024]   (3xBF16, 16 CTA)
    mma3bf_gemm_nt<64, 64, 32, 32, 16><<<dim3(Hq / 64, 1), 256>>>(
        h0, attn_W, hW, Bq, Hq, Hq, attn_Wb);

    // 2) fused energy GEMM (3xBF16) + score partials
    tgemm_score_kernel<<<dim3(Hq / 64, SBq / 128), 256>>>(
        enc, attn_U, attn_Ub, attn_v);

    // 3) attn = softmax(reduce(spart)) -> output region
    softmax_kernel<<<Bq, Sq>>>(o_attn);

    // 4) context = attn @ enc                    [64, 1024]
    context_kernel<<<Bq * Hq / 256, 256>>>(o_attn, enc);

    // 5) x2 = [emb[seq] ; ctx ; h0]              [64, 2560]
    xbuild_kernel<<<Bq * K2q / 256, 256>>>(seq, emb, h0);

    // 6) gates = x2 @ [W_ih;W_hh]^T + b_ih + b_hh  (fused, 64 CTA)
    gates_kernel<<<dim3(G4q / 64, 1), 256>>>(W_ih, W_hh, b_ih, b_hh);

    // 7) LSTM pointwise -> h_new, c_new in output
    lstm_kernel<<<Bq * Hq / 256, 256>>>(c0, o_h, o_c);

    // 8) logits = h_new @ out_W^T + out_b        (single bf16)
    logits_kernel<<<dim3((Vq + 127) / 128, 1), 256>>>(
        o_h, out_W, o_logits, out_b);

    // 9) log_softmax: partials then apply (512 blocks each)
    ls_partial_kernel<<<dim3(Bq, 8), 256>>>(o_logits);
    ls_apply_kernel<<<dim3(Bq, 8), 256>>>(o_logits);
}

// round 13
// speedup vs baseline: 1.5034x; 1.0601x over previous
#include <cuda_runtime.h>
#include <cuda_bf16.h>
#include <math.h>
#include <stdint.h>

#define Bq 64
#define Sq 128
#define Eq 512
#define Hq 1024
#define Vq 50257
#define K2q 2560        /* E + H + H : fused gates K */
#define G4q (4 * Hq)
#define SBq (Sq * Bq)
#define NSLOT 32
#define LSC 6304

// ---------------- scratch (static device globals; no runtime allocation) ----
__device__ float g_hW[Bq * Hq];
__device__ float g_spart[NSLOT * SBq];
__device__ float g_ctx[Bq * Hq];
__device__ float g_x2[Bq * K2q];
__device__ float g_gates[Bq * G4q];
__device__ float g_lsm[Bq * 8];
__device__ float g_lss[Bq * 8];
__device__ uint2 g_es[SBq * 512];      // enc pre-split: hi/lo bf16x2 pairs
__device__ uint2 g_us[Hq * 512];       // U pre-split

// ---------------- helpers ---------------------------------------------------
__device__ __forceinline__ uint32_t smem_u32(const void* p)
{
    uint32_t a;
    asm("{ .reg .u64 t; cvta.to.shared.u64 t, %1; cvt.u32.u64 %0, t; }"
        : "=r"(a) : "l"(p));
    return a;
}

__device__ __forceinline__ void split_bf16(float x, float& hi, float& lo)
{
    hi = __bfloat162float(__float2bfloat16(x));
    lo = x - hi;
}

__device__ __forceinline__ unsigned pack2(float e0, float e1)
{
    unsigned r;
    asm("cvt.rn.bf16x2.f32 %0, %1, %2;" : "=r"(r) : "f"(e1), "f"(e0));
    return r;
}

__device__ __forceinline__ void mma_bf16(float c[4], const unsigned a[4],
                                         const unsigned b[2])
{
    asm volatile(
        "mma.sync.aligned.m16n8k16.row.col.f32.bf16.bf16.f32 "
        "{%0,%1,%2,%3}, {%4,%5,%6,%7}, {%8,%9}, {%0,%1,%2,%3};"
        : "+f"(c[0]), "+f"(c[1]), "+f"(c[2]), "+f"(c[3])
        : "r"(a[0]), "r"(a[1]), "r"(a[2]), "r"(a[3]), "r"(b[0]), "r"(b[1]));
}

__device__ __forceinline__ float tanh_fast(float x)
{
    float cx = fminf(fmaxf(x, -15.f), 15.f);
    float e = __expf(2.f * cx);
    return __fdividef(e - 1.f, e + 1.f);
}

__device__ __forceinline__ void cp16(uint32_t dst, const void* src, int src_ok)
{
    asm volatile("cp.async.cg.shared.global [%0], [%1], 16, %2;"
                 :: "r"(dst), "l"(src), "r"(src_ok ? 16 : 0) : "memory");
}
__device__ __forceinline__ void cp_commit()
{
    asm volatile("cp.async.commit_group;" ::: "memory");
}
template <int N>
__device__ __forceinline__ void cp_wait()
{
    asm volatile("cp.async.wait_group %0;" :: "n"(N) : "memory");
}

// ================== pre-split kernels: fp32 -> hi/lo bf16x2 uint2 ===========
// Each thread handles one float4 (2 pairs). dst[r][p] over P=512 pairs/row.
__global__ void presplit_kernel_enc(const float* __restrict__ src)
{
    size_t i = (size_t)blockIdx.x * 256 + threadIdx.x;   // float4 index
    float4 v = reinterpret_cast<const float4*>(src)[i];
    float hx, lx, hy, ly, hz, lz, hw, lw;
    split_bf16(v.x, hx, lx); split_bf16(v.y, hy, ly);
    split_bf16(v.z, hz, lz); split_bf16(v.w, hw, lw);
    g_es[2 * i]     = make_uint2(pack2(hx, hy), pack2(lx, ly));
    g_es[2 * i + 1] = make_uint2(pack2(hz, hw), pack2(lz, lw));
}

__global__ void presplit_kernel_u(const float* __restrict__ src)
{
    size_t i = (size_t)blockIdx.x * 256 + threadIdx.x;
    float4 v = reinterpret_cast<const float4*>(src)[i];
    float hx, lx, hy, ly, hz, lz, hw, lw;
    split_bf16(v.x, hx, lx); split_bf16(v.y, hy, ly);
    split_bf16(v.z, hz, lz); split_bf16(v.w, hw, lw);
    g_us[2 * i]     = make_uint2(pack2(hx, hy), pack2(lx, ly));
    g_us[2 * i + 1] = make_uint2(pack2(hz, hw), pack2(lz, lw));
}

// ============ T GEMM (pre-split, cp.async 4-stage) + fused score ============
// T = enc[8192,1024] @ U[1024,1024]^T; score partials out (32 slots).
// BM=128, BN=64, BK=32 (16 pairs); warp grid 4(M)x2(N), warp tile 32x32.
#define TS_ROWP 18                      /* uint2 per row (16 data + 2 pad) */
#define TS_B (128 * TS_ROWP)            /* B offset in uint2 */
#define TS_STG (192 * TS_ROWP)          /* uint2 per stage = 3456 */
#define TS_SMEM (4 * TS_STG * 8)        /* 110592 B */

__global__ void __launch_bounds__(256, 2)
tgemm_score_kernel(const float* __restrict__ Ub, const float* __restrict__ v)
{
    extern __shared__ uint2 smt[];
    constexpr int MI = 2, NI = 4;

    const int tid = threadIdx.x;
    const int lane = tid & 31;
    const int w = tid >> 5;
    const int lane4 = lane >> 2;
    const int lanek = lane & 3;
    const int warp_m = (w & 3) * 32;
    const int warp_n = (w >> 2) * 32;
    const int m0 = blockIdx.y * 128;
    const int n0 = blockIdx.x * 64;

    float acc[MI][NI][4];
#pragma unroll
    for (int i = 0; i < MI; i++)
#pragma unroll
        for (int j = 0; j < NI; j++)
#pragma unroll
            for (int q = 0; q < 4; q++) acc[i][j][q] = 0.f;

    auto issue = [&](int ch) {
        uint2* st = smt + (ch & 3) * TS_STG;
        uint32_t sb = smem_u32(st);
        int k16 = ch * 16;
#pragma unroll
        for (int u = 0; u < 4; u++) {
            int i = tid + 256 * u;
            int row = i >> 3;
            int pe = (i & 7) * 2;
            cp16(sb + (uint32_t)(row * TS_ROWP + pe) * 8,
                 &g_es[(size_t)(m0 + row) * 512 + k16 + pe], 1);
        }
#pragma unroll
        for (int u = 0; u < 2; u++) {
            int i = tid + 256 * u;
            int row = i >> 3;
            int pe = (i & 7) * 2;
            cp16(sb + (uint32_t)(TS_B + row * TS_ROWP + pe) * 8,
                 &g_us[(size_t)(n0 + row) * 512 + k16 + pe], 1);
        }
        cp_commit();
    };

    issue(0); issue(1); issue(2);

    for (int ch = 0; ch < 32; ch++) {
        cp_wait<2>();
        __syncthreads();
        const uint2* st = smt + (ch & 3) * TS_STG;

#pragma unroll
        for (int kk = 0; kk < 16; kk += 8) {
            unsigned ah[MI][4], al[MI][4], bh[NI][2], bl[NI][2];
#pragma unroll
            for (int i = 0; i < MI; i++) {
                int r = warp_m + i * 16 + lane4;
                int cb = kk + lanek;
                uint2 t0 = st[r * TS_ROWP + cb];
                uint2 t1 = st[(r + 8) * TS_ROWP + cb];
                uint2 t2 = st[r * TS_ROWP + cb + 4];
                uint2 t3 = st[(r + 8) * TS_ROWP + cb + 4];
                ah[i][0] = t0.x; al[i][0] = t0.y;
                ah[i][1] = t1.x; al[i][1] = t1.y;
                ah[i][2] = t2.x; al[i][2] = t2.y;
                ah[i][3] = t3.x; al[i][3] = t3.y;
            }
#pragma unroll
            for (int j = 0; j < NI; j++) {
                int r = warp_n + j * 8 + lane4;
                int cb = kk + lanek;
                uint2 t0 = st[TS_B + r * TS_ROWP + cb];
                uint2 t1 = st[TS_B + r * TS_ROWP + cb + 4];
                bh[j][0] = t0.x; bl[j][0] = t0.y;
                bh[j][1] = t1.x; bl[j][1] = t1.y;
            }
#pragma unroll
            for (int i = 0; i < MI; i++)
#pragma unroll
                for (int j = 0; j < NI; j++) {
                    mma_bf16(acc[i][j], ah[i], bl[j]);
                    mma_bf16(acc[i][j], al[i], bh[j]);
                    mma_bf16(acc[i][j], ah[i], bh[j]);
                }
        }

        if (ch + 3 < 32) issue(ch + 3);
        else cp_commit();
        __syncthreads();
    }

    // ---- fused score epilogue over this warp's 32 columns ------------------
    float vv[NI][2], uu[NI][2];
#pragma unroll
    for (int j = 0; j < NI; j++)
#pragma unroll
        for (int qc = 0; qc < 2; qc++) {
            int c = n0 + warp_n + j * 8 + 2 * lanek + qc;
            vv[j][qc] = v[c];
            uu[j][qc] = Ub[c];
        }

    const int slot = blockIdx.x * 2 + (w >> 2);
#pragma unroll
    for (int i = 0; i < MI; i++)
#pragma unroll
        for (int qr = 0; qr < 2; qr++) {
            int row = m0 + warp_m + i * 16 + lane4 + qr * 8;
            int b = row & (Bq - 1);
            const float* hwr = g_hW + (size_t)b * Hq + n0 + warp_n + 2 * lanek;
            float part = 0.f;
#pragma unroll
            for (int j = 0; j < NI; j++)
#pragma unroll
                for (int qc = 0; qc < 2; qc++) {
                    float t = acc[i][j][2 * qr + qc] + uu[j][qc]
                              + hwr[j * 8 + qc];
                    part += vv[j][qc] * tanh_fast(t);
                }
            part += __shfl_xor_sync(0xffffffffu, part, 1);
            part += __shfl_xor_sync(0xffffffffu, part, 2);
            if (lanek == 0)
                g_spart[(size_t)slot * SBq + row] = part;
        }
}

// ================== 3xBF16 GEMM template (hW) ===============================
template <int BM, int BN, int BK, int WM, int WN>
__global__ void __launch_bounds__(256)
mma3bf_gemm_nt(const float* __restrict__ A, const float* __restrict__ Bm,
               float* __restrict__ C, int M, int N, int K,
               const float* __restrict__ bias)
{
    constexpr int MI = WM / 16;
    constexpr int NI = WN / 8;
    constexpr int PP = BK / 2;
    constexpr int KPP = PP + 4;
    constexpr int F4R = BK / 4;
    constexpr int RPP = 256 / F4R;

    __shared__ uint2 Aa[BM][KPP];
    __shared__ uint2 Ba[BN][KPP];

    const int tid = threadIdx.x;
    const int lane = tid & 31;
    const int w = tid >> 5;
    const int warp_m = (w % (BM / WM)) * WM;
    const int warp_n = (w / (BM / WM)) * WN;
    const int m0 = blockIdx.y * BM;
    const int n0 = blockIdx.x * BN;
    const int lrow = tid / F4R;
    const int lk4 = (tid % F4R) * 4;
    const int lp = lk4 >> 1;

    float acc[MI][NI][4];
#pragma unroll
    for (int i = 0; i < MI; i++)
#pragma unroll
        for (int j = 0; j < NI; j++)
#pragma unroll
            for (int q = 0; q < 4; q++) acc[i][j][q] = 0.f;

    for (int k0 = 0; k0 < K; k0 += BK) {
#pragma unroll
        for (int r = lrow; r < BM; r += RPP) {
            float4 vv = *reinterpret_cast<const float4*>(
                A + (size_t)(m0 + r) * K + k0 + lk4);
            float hx, lx, hy, ly, hz, lz, hw, lw;
            split_bf16(vv.x, hx, lx); split_bf16(vv.y, hy, ly);
            split_bf16(vv.z, hz, lz); split_bf16(vv.w, hw, lw);
            Aa[r][lp]     = make_uint2(pack2(hx, hy), pack2(lx, ly));
            Aa[r][lp + 1] = make_uint2(pack2(hz, hw), pack2(lz, lw));
        }
#pragma unroll
        for (int r = lrow; r < BN; r += RPP) {
            float4 vv = make_float4(0.f, 0.f, 0.f, 0.f);
            if (n0 + r < N)
                vv = *reinterpret_cast<const float4*>(
                    Bm + (size_t)(n0 + r) * K + k0 + lk4);
            float hx, lx, hy, ly, hz, lz, hw, lw;
            split_bf16(vv.x, hx, lx); split_bf16(vv.y, hy, ly);
            split_bf16(vv.z, hz, lz); split_bf16(vv.w, hw, lw);
            Ba[r][lp]     = make_uint2(pack2(hx, hy), pack2(lx, ly));
            Ba[r][lp + 1] = make_uint2(pack2(hz, hw), pack2(lz, lw));
        }
        __syncthreads();

#pragma unroll
        for (int kk = 0; kk < PP; kk += 8) {
            unsigned ah[MI][4], al[MI][4], bh[NI][2], bl[NI][2];
#pragma unroll
            for (int i = 0; i < MI; i++) {
                int r = warp_m + i * 16 + (lane >> 2);
                int cb = kk + (lane & 3);
                uint2 t0 = Aa[r][cb];      ah[i][0] = t0.x; al[i][0] = t0.y;
                uint2 t1 = Aa[r + 8][cb];  ah[i][1] = t1.x; al[i][1] = t1.y;
                uint2 t2 = Aa[r][cb + 4];  ah[i][2] = t2.x; al[i][2] = t2.y;
                uint2 t3 = Aa[r + 8][cb + 4]; ah[i][3] = t3.x; al[i][3] = t3.y;
            }
#pragma unroll
            for (int j = 0; j < NI; j++) {
                int r = warp_n + j * 8 + (lane >> 2);
                int cb = kk + (lane & 3);
                uint2 t0 = Ba[r][cb];      bh[j][0] = t0.x; bl[j][0] = t0.y;
                uint2 t1 = Ba[r][cb + 4];  bh[j][1] = t1.x; bl[j][1] = t1.y;
            }
#pragma unroll
            for (int i = 0; i < MI; i++)
#pragma unroll
                for (int j = 0; j < NI; j++) {
                    mma_bf16(acc[i][j], ah[i], bl[j]);
                    mma_bf16(acc[i][j], al[i], bh[j]);
                    mma_bf16(acc[i][j], ah[i], bh[j]);
                }
        }
        __syncthreads();
    }

#pragma unroll
    for (int i = 0; i < MI; i++)
#pragma unroll
        for (int j = 0; j < NI; j++) {
            int row = m0 + warp_m + i * 16 + (lane >> 2);
            int col = n0 + warp_n + j * 8 + 2 * (lane & 3);
#pragma unroll
            for (int q = 0; q < 4; q++) {
                int gr = row + (q >> 1) * 8;
                int gc = col + (q & 1);
                if (gc < N) {
                    float r = acc[i][j][q];
                    if (bias) r += bias[gc];
                    C[(size_t)gr * N + gc] = r;
                }
            }
        }
}

// ============ fused gates GEMM: [x2] @ [W_ih;W_hh]^T, K=2560, 3xBF16 ========
__global__ void __launch_bounds__(256)
gates_kernel(const float* __restrict__ W1, const float* __restrict__ W2,
             const float* __restrict__ b1, const float* __restrict__ b2)
{
    constexpr int BM = 64, BN = 64, BK = 32;
    constexpr int MI = 2, NI = 2;
    constexpr int PP = 16, KPP = 20;

    __shared__ uint2 Aa[BM][KPP];
    __shared__ uint2 Ba[BN][KPP];

    const int tid = threadIdx.x;
    const int lane = tid & 31;
    const int w = tid >> 5;
    const int warp_m = (w % 2) * 32;
    const int warp_n = (w / 2) * 16;
    const int n0 = blockIdx.x * BN;
    const int lrow = tid >> 3;
    const int lk4 = (tid & 7) * 4;
    const int lp = lk4 >> 1;

    float acc[MI][NI][4];
#pragma unroll
    for (int i = 0; i < MI; i++)
#pragma unroll
        for (int j = 0; j < NI; j++)
#pragma unroll
            for (int q = 0; q < 4; q++) acc[i][j][q] = 0.f;

    for (int k0 = 0; k0 < K2q; k0 += BK) {
#pragma unroll
        for (int r = lrow; r < BM; r += 32) {
            float4 vv = *reinterpret_cast<const float4*>(
                g_x2 + (size_t)r * K2q + k0 + lk4);
            float hx, lx, hy, ly, hz, lz, hw, lw;
            split_bf16(vv.x, hx, lx); split_bf16(vv.y, hy, ly);
            split_bf16(vv.z, hz, lz); split_bf16(vv.w, hw, lw);
            Aa[r][lp]     = make_uint2(pack2(hx, hy), pack2(lx, ly));
            Aa[r][lp + 1] = make_uint2(pack2(hz, hw), pack2(lz, lw));
        }
#pragma unroll
        for (int r = lrow; r < BN; r += 32) {
            const float* src = (k0 < 1536)
                ? W1 + (size_t)(n0 + r) * 1536 + k0 + lk4
                : W2 + (size_t)(n0 + r) * Hq + (k0 - 1536) + lk4;
            float4 vv = *reinterpret_cast<const float4*>(src);
            float hx, lx, hy, ly, hz, lz, hw, lw;
            split_bf16(vv.x, hx, lx); split_bf16(vv.y, hy, ly);
            split_bf16(vv.z, hz, lz); split_bf16(vv.w, hw, lw);
            Ba[r][lp]     = make_uint2(pack2(hx, hy), pack2(lx, ly));
            Ba[r][lp + 1] = make_uint2(pack2(hz, hw), pack2(lz, lw));
        }
        __syncthreads();

#pragma unroll
        for (int kk = 0; kk < PP; kk += 8) {
            unsigned ah[MI][4], al[MI][4], bh[NI][2], bl[NI][2];
#pragma unroll
            for (int i = 0; i < MI; i++) {
                int r = warp_m + i * 16 + (lane >> 2);
                int cb = kk + (lane & 3);
                uint2 t0 = Aa[r][cb];      ah[i][0] = t0.x; al[i][0] = t0.y;
                uint2 t1 = Aa[r + 8][cb];  ah[i][1] = t1.x; al[i][1] = t1.y;
                uint2 t2 = Aa[r][cb + 4];  ah[i][2] = t2.x; al[i][2] = t2.y;
                uint2 t3 = Aa[r + 8][cb + 4]; ah[i][3] = t3.x; al[i][3] = t3.y;
            }
#pragma unroll
            for (int j = 0; j < NI; j++) {
                int r = warp_n + j * 8 + (lane >> 2);
                int cb = kk + (lane & 3);
                uint2 t0 = Ba[r][cb];      bh[j][0] = t0.x; bl[j][0] = t0.y;
                uint2 t1 = Ba[r][cb + 4];  bh[j][1] = t1.x; bl[j][1] = t1.y;
            }
#pragma unroll
            for (int i = 0; i < MI; i++)
#pragma unroll
                for (int j = 0; j < NI; j++) {
                    mma_bf16(acc[i][j], ah[i], bl[j]);
                    mma_bf16(acc[i][j], al[i], bh[j]);
                    mma_bf16(acc[i][j], ah[i], bh[j]);
                }
        }
        __syncthreads();
    }

#pragma unroll
    for (int i = 0; i < MI; i++)
#pragma unroll
        for (int j = 0; j < NI; j++) {
            int row = warp_m + i * 16 + (lane >> 2);
            int col = n0 + warp_n + j * 8 + 2 * (lane & 3);
#pragma unroll
            for (int q = 0; q < 4; q++) {
                int gr = row + (q >> 1) * 8;
                int gc = col + (q & 1);
                g_gates[(size_t)gr * G4q + gc] =
                    acc[i][j][q] + b1[gc] + b2[gc];
            }
        }
}

// ====== logits GEMM: single-pass bf16 m16n8k16 (R12, proven) ================
__global__ void __launch_bounds__(256)
logits_kernel(const float* __restrict__ A, const float* __restrict__ Bm,
              float* __restrict__ C, const float* __restrict__ bias)
{
    constexpr int BM = 64, BN = 128, BK = 32;
    constexpr int MI = 2, NI = 4;
    constexpr int PP = 16, KPP = 20;
    const int N = Vq, K = Hq;

    __shared__ unsigned Aa[BM][KPP];
    __shared__ unsigned Ba[BN][KPP];

    const int tid = threadIdx.x;
    const int lane = tid & 31;
    const int w = tid >> 5;
    const int warp_m = (w & 1) * 32;
    const int warp_n = (w >> 1) * 32;
    const int n0 = blockIdx.x * BN;
    const int lrow = tid >> 3;
    const int lk4 = (tid & 7) * 4;
    const int lp = lk4 >> 1;

    float acc[MI][NI][4];
#pragma unroll
    for (int i = 0; i < MI; i++)
#pragma unroll
        for (int j = 0; j < NI; j++)
#pragma unroll
            for (int q = 0; q < 4; q++) acc[i][j][q] = 0.f;

    for (int k0 = 0; k0 < K; k0 += BK) {
#pragma unroll
        for (int r = lrow; r < BM; r += 32) {
            float4 vv = *reinterpret_cast<const float4*>(
                A + (size_t)r * K + k0 + lk4);
            Aa[r][lp]     = pack2(vv.x, vv.y);
            Aa[r][lp + 1] = pack2(vv.z, vv.w);
        }
#pragma unroll
        for (int r = lrow; r < BN; r += 32) {
            float4 vv = make_float4(0.f, 0.f, 0.f, 0.f);
            if (n0 + r < N)
                vv = *reinterpret_cast<const float4*>(
                    Bm + (size_t)(n0 + r) * K + k0 + lk4);
            Ba[r][lp]     = pack2(vv.x, vv.y);
            Ba[r][lp + 1] = pack2(vv.z, vv.w);
        }
        __syncthreads();

#pragma unroll
        for (int kk = 0; kk < PP; kk += 8) {
            unsigned af[MI][4], bf[NI][2];
#pragma unroll
            for (int i = 0; i < MI; i++) {
                int r = warp_m + i * 16 + (lane >> 2);
                int cb = kk + (lane & 3);
                af[i][0] = Aa[r][cb];     af[i][1] = Aa[r + 8][cb];
                af[i][2] = Aa[r][cb + 4]; af[i][3] = Aa[r + 8][cb + 4];
            }
#pragma unroll
            for (int j = 0; j < NI; j++) {
                int r = warp_n + j * 8 + (lane >> 2);
                int cb = kk + (lane & 3);
                bf[j][0] = Ba[r][cb]; bf[j][1] = Ba[r][cb + 4];
            }
#pragma unroll
            for (int i = 0; i < MI; i++)
#pragma unroll
                for (int j = 0; j < NI; j++)
                    mma_bf16(acc[i][j], af[i], bf[j]);
        }
        __syncthreads();
    }

#pragma unroll
    for (int i = 0; i < MI; i++)
#pragma unroll
        for (int j = 0; j < NI; j++) {
            int row = warp_m + i * 16 + (lane >> 2);
            int col = n0 + warp_n + j * 8 + 2 * (lane & 3);
#pragma unroll
            for (int q = 0; q < 4; q++) {
                int gr = row + (q >> 1) * 8;
                int gc = col + (q & 1);
                if (gc < N)
                    C[(size_t)gr * N + gc] = acc[i][j][q] + bias[gc];
            }
        }
}

// ---------------- pointwise / reduction kernels -----------------------------
__global__ void softmax_kernel(float* __restrict__ attn_out)
{
    __shared__ float sm[Sq];
    int b = blockIdx.x, t = threadIdx.x;
    float x = 0.f;
#pragma unroll
    for (int q = 0; q < NSLOT; q++)
        x += g_spart[(size_t)q * SBq + t * Bq + b];
    sm[t] = x; __syncthreads();
    for (int o = 64; o > 0; o >>= 1) {
        if (t < o) sm[t] = fmaxf(sm[t], sm[t + o]);
        __syncthreads();
    }
    float m = sm[0];
    __syncthreads();
    float e = expf(x - m);
    sm[t] = e; __syncthreads();
    for (int o = 64; o > 0; o >>= 1) {
        if (t < o) sm[t] += sm[t + o];
        __syncthreads();
    }
    attn_out[b * Sq + t] = e / sm[0];
}

__global__ void context_kernel(const float* __restrict__ attn,
                               const float* __restrict__ enc)
{
    __shared__ float aw[Sq];
    int idx = blockIdx.x * 256 + threadIdx.x;
    int b = idx >> 10;
    int h = idx & (Hq - 1);
    if (threadIdx.x < Sq) aw[threadIdx.x] = attn[b * Sq + threadIdx.x];
    __syncthreads();
    float acc = 0.f;
#pragma unroll 8
    for (int s = 0; s < Sq; s++)
        acc = fmaf(aw[s], enc[((size_t)s * Bq + b) * Hq + h], acc);
    g_ctx[idx] = acc;
}

__global__ void xbuild_kernel(const int* __restrict__ seq,
                              const float* __restrict__ emb,
                              const float* __restrict__ h0)
{
    int idx = blockIdx.x * 256 + threadIdx.x;
    int b = idx / K2q;
    int j = idx - b * K2q;
    float val;
    if (j < Eq)            val = emb[(size_t)seq[b] * Eq + j];
    else if (j < Eq + Hq)  val = g_ctx[b * Hq + (j - Eq)];
    else                   val = h0[b * Hq + (j - Eq - Hq)];
    g_x2[idx] = val;
}

__device__ __forceinline__ float sigf(float x) { return 1.f / (1.f + expf(-x)); }

__global__ void lstm_kernel(const float* __restrict__ c0,
                            float* __restrict__ h_new,
                            float* __restrict__ c_new)
{
    int idx = blockIdx.x * 256 + threadIdx.x;
    int b = idx >> 10;
    int h = idx & (Hq - 1);
    const float* g = g_gates + ((size_t)b << 12);
    float vi = g[h];
    float vf = g[Hq + h];
    float vg = g[2 * Hq + h];
    float vo = g[3 * Hq + h];
    float c = sigf(vf) * c0[idx] + sigf(vi) * tanhf(vg);
    c_new[idx] = c;
    h_new[idx] = sigf(vo) * tanhf(c);
}

// ---- two-phase log-softmax -------------------------------------------------
__global__ void ls_partial_kernel(const float* __restrict__ out)
{
    __shared__ float red[8];
    int b = blockIdx.x, c = blockIdx.y, t = threadIdx.x;
    const float* row = out + (size_t)b * Vq;
    int j0 = c * LSC;
    int j1 = min(j0 + LSC, Vq);

    float m = -1e30f;
    for (int j = j0 + t; j < j1; j += 256) m = fmaxf(m, row[j]);
#pragma unroll
    for (int o = 16; o > 0; o >>= 1) m = fmaxf(m, __shfl_xor_sync(~0u, m, o));
    if ((t & 31) == 0) red[t >> 5] = m;
    __syncthreads();
    if (t < 32) {
        float v = (t < 8) ? red[t] : -1e30f;
#pragma unroll
        for (int o = 4; o > 0; o >>= 1) v = fmaxf(v, __shfl_xor_sync(~0u, v, o));
        if (t == 0) red[0] = v;
    }
    __syncthreads();
    m = red[0];
    __syncthreads();

    float s = 0.f;
    for (int j = j0 + t; j < j1; j += 256) s += expf(row[j] - m);
#pragma unroll
    for (int o = 16; o > 0; o >>= 1) s += __shfl_xor_sync(~0u, s, o);
    if ((t & 31) == 0) red[t >> 5] = s;
    __syncthreads();
    if (t < 32) {
        float v = (t < 8) ? red[t] : 0.f;
#pragma unroll
        for (int o = 4; o > 0; o >>= 1) v += __shfl_xor_sync(~0u, v, o);
        if (t == 0) {
            g_lsm[b * 8 + c] = m;
            g_lss[b * 8 + c] = v;
        }
    }
}

__global__ void ls_apply_kernel(float* __restrict__ out)
{
    int b = blockIdx.x, c = blockIdx.y, t = threadIdx.x;
    float M = -1e30f;
#pragma unroll
    for (int q = 0; q < 8; q++) M = fmaxf(M, g_lsm[b * 8 + q]);
    float S = 0.f;
#pragma unroll
    for (int q = 0; q < 8; q++)
        S += g_lss[b * 8 + q] * expf(g_lsm[b * 8 + q] - M);
    float lse = M + logf(S);

    float* row = out + (size_t)b * Vq;
    int j0 = c * LSC;
    int j1 = min(j0 + LSC, Vq);
    for (int j = j0 + t; j < j1; j += 256) row[j] -= lse;
}

// ---------------------------------------------------------------------------
extern "C" void kernel_launch(void* const* d_in, const int* in_sizes, int n_in,
                              void* d_out, int out_size)
{
    const int*   seq     = (const int*)d_in[0];
    const float* h0      = (const float*)d_in[1];
    const float* c0      = (const float*)d_in[2];
    const float* enc     = (const float*)d_in[3];
    const float* emb     = (const float*)d_in[4];
    const float* W_ih    = (const float*)d_in[5];
    const float* W_hh    = (const float*)d_in[6];
    const float* b_ih    = (const float*)d_in[7];
    const float* b_hh    = (const float*)d_in[8];
    const float* attn_W  = (const float*)d_in[9];
    const float* attn_Wb = (const float*)d_in[10];
    const float* attn_U  = (const float*)d_in[11];
    const float* attn_Ub = (const float*)d_in[12];
    const float* attn_v  = (const float*)d_in[13];
    const float* out_W   = (const float*)d_in[14];
    const float* out_b   = (const float*)d_in[15];

    float* out      = (float*)d_out;
    float* o_logits = out;                          // [B, V]
    float* o_h      = out + (size_t)Bq * Vq;        // [1, B, H]
    float* o_c      = o_h + Bq * Hq;                // [1, B, H]
    float* o_attn   = o_c + Bq * Hq;                // [B, 1, S]

    float* hW;
    cudaGetSymbolAddress((void**)&hW, g_hW);

    cudaFuncSetAttribute(tgemm_score_kernel,
                         cudaFuncAttributeMaxDynamicSharedMemorySize, TS_SMEM);

    // 1) hW = h0 @ attn_W^T + attn_Wb            [64, 1024]  (3xBF16, 16 CTA)
    mma3bf_gemm_nt<64, 64, 32, 32, 16><<<dim3(Hq / 64, 1), 256>>>(
        h0, attn_W, hW, Bq, Hq, Hq, attn_Wb);

    // 2-3) pre-split enc and U to hi/lo bf16x2 pairs
    presplit_kernel_enc<<<SBq * Hq / 1024, 256>>>(enc);
    presplit_kernel_u<<<Hq * Hq / 1024, 256>>>(attn_U);

    // 4) T GEMM (pre-split, cp.async pipelined) + fused score  [launch #4]
    tgemm_score_kernel<<<dim3(Hq / 64, SBq / 128), 256, TS_SMEM>>>(
        attn_Ub, attn_v);

    // 5) attn = softmax(reduce(spart)) -> output region
    softmax_kernel<<<Bq, Sq>>>(o_attn);

    // 6) context = attn @ enc                    [64, 1024]
    context_kernel<<<Bq * Hq / 256, 256>>>(o_attn, enc);

    // 7) x2 = [emb[seq] ; ctx ; h0]              [64, 2560]
    xbuild_kernel<<<Bq * K2q / 256, 256>>>(seq, emb, h0);

    // 8) gates = x2 @ [W_ih;W_hh]^T + biases     (fused, 64 CTA)
    gates_kernel<<<dim3(G4q / 64, 1), 256>>>(W_ih, W_hh, b_ih, b_hh);

    // 9) LSTM pointwise -> h_new, c_new in output
    lstm_kernel<<<Bq * Hq / 256, 256>>>(c0, o_h, o_c);

    // 10) logits = h_new @ out_W^T + out_b       (single bf16)
    logits_kernel<<<dim3((Vq + 127) / 128, 1), 256>>>(
        o_h, out_W, o_logits, out_b);

    // 11-12) log_softmax: partials then apply
    ls_partial_kernel<<<dim3(Bq, 8), 256>>>(o_logits);
    ls_apply_kernel<<<dim3(Bq, 8), 256>>>(o_logits);
}